// round 1
// baseline (speedup 1.0000x reference)
#include <cuda_runtime.h>
#include <math.h>

#define B_   8
#define S_   1024
#define H_   512
#define NH_  8
#define DH_  64
#define FFN_ 2048
#define M_   (B_*S_)

// ---------------- scratch (device globals; no allocation allowed) ----------------
__device__ float g_y  [M_*H_];
__device__ float g_q  [M_*H_];
__device__ float g_k  [M_*H_];
__device__ float g_v  [M_*H_];
__device__ float g_att[M_*H_];
__device__ float g_x1 [M_*H_];
__device__ float g_h1 [M_*FFN_];

// ---------------- LayerNorm: one row (H=512) per 256-thread block ----------------
__global__ __launch_bounds__(256) void ln_kernel(
    const float* __restrict__ x, const float* __restrict__ gam,
    const float* __restrict__ bet, float* __restrict__ y)
{
    int row = blockIdx.x;
    int t   = threadIdx.x;
    const float* xr = x + (long)row * H_;
    float a = xr[t];
    float b = xr[t + 256];
    float s = a + b;
    float q = a * a + b * b;
    #pragma unroll
    for (int off = 16; off > 0; off >>= 1) {
        s += __shfl_xor_sync(0xffffffffu, s, off);
        q += __shfl_xor_sync(0xffffffffu, q, off);
    }
    __shared__ float ss[8], qq[8];
    int w = t >> 5, lane = t & 31;
    if (lane == 0) { ss[w] = s; qq[w] = q; }
    __syncthreads();
    float S = 0.f, Q = 0.f;
    #pragma unroll
    for (int i = 0; i < 8; i++) { S += ss[i]; Q += qq[i]; }
    float mean = S * (1.f / H_);
    float var  = Q * (1.f / H_) - mean * mean;
    float inv  = rsqrtf(var + 1e-5f);
    float* yr = y + (long)row * H_;
    yr[t]       = (a - mean) * inv * gam[t]       + bet[t];
    yr[t + 256] = (b - mean) * inv * gam[t + 256] + bet[t + 256];
}

// ---------------- GEMM: C = A[M,K] @ W[K,N] (+bias, epilogue by MODE) ----------------
// MODE 0: QKV scatter  out[((b*NH+h)*S+s)*DH+d], b=m/S, s=m%S, h=n/DH, d=n%DH
// MODE 1: residual     out[m*N+n] = res[m*N+n] + acc + bias[n]
// MODE 2: exact GELU   out[m*N+n] = gelu(acc + bias[n])
template<int MODE>
__global__ __launch_bounds__(256) void gemm_kernel(
    const float* __restrict__ A, const float* __restrict__ Bm,
    const float* __restrict__ bias, const float* __restrict__ res,
    float* __restrict__ Cout, int Md, int Nd, int Kd)
{
    __shared__ float As[16][132];   // padded to dodge store conflicts
    __shared__ float Bs[16][128];
    int tid = threadIdx.x;
    int bx = blockIdx.x, by = blockIdx.y;
    int tx = tid & 15, ty = tid >> 4;

    float acc[8][8];
    #pragma unroll
    for (int i = 0; i < 8; i++)
        #pragma unroll
        for (int j = 0; j < 8; j++) acc[i][j] = 0.f;

    int aRow = tid >> 2;            // 0..63 (two rows per thread: +0, +64)
    int aCol = (tid & 3) << 2;      // 0,4,8,12
    int bRow = tid >> 5;            // 0..7  (two rows per thread: +0, +8)
    int bCol = (tid & 31) << 2;     // 0..124

    const float* Abase = A  + (long)(by * 128) * Kd;
    const float* Bbase = Bm + bx * 128;

    for (int k0 = 0; k0 < Kd; k0 += 16) {
        float4 a0 = *(const float4*)(Abase + (long)aRow        * Kd + k0 + aCol);
        float4 a1 = *(const float4*)(Abase + (long)(aRow + 64) * Kd + k0 + aCol);
        float4 b0 = *(const float4*)(Bbase + (long)(k0 + bRow)     * Nd + bCol);
        float4 b1 = *(const float4*)(Bbase + (long)(k0 + bRow + 8) * Nd + bCol);
        As[aCol + 0][aRow] = a0.x;  As[aCol + 1][aRow] = a0.y;
        As[aCol + 2][aRow] = a0.z;  As[aCol + 3][aRow] = a0.w;
        As[aCol + 0][aRow + 64] = a1.x;  As[aCol + 1][aRow + 64] = a1.y;
        As[aCol + 2][aRow + 64] = a1.z;  As[aCol + 3][aRow + 64] = a1.w;
        *(float4*)&Bs[bRow][bCol]     = b0;
        *(float4*)&Bs[bRow + 8][bCol] = b1;
        __syncthreads();
        #pragma unroll
        for (int kk = 0; kk < 16; kk++) {
            float ra[8], rb[8];
            *(float4*)&ra[0] = *(const float4*)&As[kk][ty * 8];
            *(float4*)&ra[4] = *(const float4*)&As[kk][ty * 8 + 4];
            *(float4*)&rb[0] = *(const float4*)&Bs[kk][tx * 8];
            *(float4*)&rb[4] = *(const float4*)&Bs[kk][tx * 8 + 4];
            #pragma unroll
            for (int i = 0; i < 8; i++)
                #pragma unroll
                for (int j = 0; j < 8; j++)
                    acc[i][j] = fmaf(ra[i], rb[j], acc[i][j]);
        }
        __syncthreads();
    }

    #pragma unroll
    for (int i = 0; i < 8; i++) {
        int mr = by * 128 + ty * 8 + i;
        #pragma unroll
        for (int j = 0; j < 8; j++) {
            int nc = bx * 128 + tx * 8 + j;
            float val = acc[i][j] + bias[nc];
            if (MODE == 0) {
                int b = mr >> 10, s = mr & 1023;      // S_=1024
                int h = nc >> 6,  d = nc & 63;        // DH_=64
                Cout[((long)((b * NH_ + h) << 10) + s) * DH_ + d] = val;
            } else if (MODE == 1) {
                long idx = (long)mr * Nd + nc;
                Cout[idx] = res[idx] + val;
            } else {
                long idx = (long)mr * Nd + nc;
                Cout[idx] = 0.5f * val * (1.f + erff(val * 0.70710678118f));
            }
        }
    }
}

// ---------------- Flash attention: 64 q-rows / block, 64-key tiles ----------------
// grid = (NH, S/64, B), 64 threads. Thread t owns query row qt*64+t end-to-end.
__global__ __launch_bounds__(64) void attn_kernel(
    const float* __restrict__ q, const float* __restrict__ k,
    const float* __restrict__ v, const float* __restrict__ bias,
    const int* __restrict__ mask, float* __restrict__ att)
{
    __shared__ float Ks[64][64];
    __shared__ float Vs[64][64];
    __shared__ float Ss[64][64];   // scores staged [key][thread] -> bank-clean

    int h = blockIdx.x, qt = blockIdx.y, b = blockIdx.z;
    int t = threadIdx.x;
    int srow = qt * 64 + t;

    const float* qp = q + ((long)((b * NH_ + h) * S_) + srow) * DH_;
    float qr[64];
    #pragma unroll
    for (int d = 0; d < 64; d++) qr[d] = qp[d] * 0.125f;   // DH^-0.5

    float o[64];
    #pragma unroll
    for (int d = 0; d < 64; d++) o[d] = 0.f;
    float mrun = -3.0e38f, l = 0.f;

    const float4* kb = (const float4*)(k + (long)((b * NH_ + h) * S_) * DH_);
    const float4* vb = (const float4*)(v + (long)((b * NH_ + h) * S_) * DH_);
    const float*  brow = bias + ((long)b * S_ + srow) * S_;
    const int*    mrow = mask + ((long)b * S_ + srow) * S_;

    for (int kt = 0; kt < S_ / 64; kt++) {
        float4* kd = (float4*)&Ks[0][0];
        float4* vd = (float4*)&Vs[0][0];
        const float4* ksrc = kb + kt * 64 * 16;
        const float4* vsrc = vb + kt * 64 * 16;
        #pragma unroll
        for (int i = 0; i < 16; i++) {
            kd[t + i * 64] = ksrc[t + i * 64];
            vd[t + i * 64] = vsrc[t + i * 64];
        }
        __syncthreads();

        int kk0 = kt * 64;
        float tmax = -3.0e38f;
        // pass 1: scores (+ bias/mask), tile max. 4 partial sums -> enough FMA chains.
        #pragma unroll 2
        for (int j = 0; j < 64; j++) {
            float s0 = 0.f, s1 = 0.f, s2 = 0.f, s3 = 0.f;
            #pragma unroll
            for (int d = 0; d < 64; d += 4) {
                s0 = fmaf(qr[d    ], Ks[j][d    ], s0);
                s1 = fmaf(qr[d + 1], Ks[j][d + 1], s1);
                s2 = fmaf(qr[d + 2], Ks[j][d + 2], s2);
                s3 = fmaf(qr[d + 3], Ks[j][d + 3], s3);
            }
            float s = (s0 + s1) + (s2 + s3);
            float sc = (mrow[kk0 + j] == 0) ? -1e9f : (s + brow[kk0 + j]);
            Ss[j][t] = sc;
            tmax = fmaxf(tmax, sc);
        }
        float mnew = fmaxf(mrun, tmax);
        float c = __expf(mrun - mnew);
        l *= c;
        #pragma unroll
        for (int d = 0; d < 64; d++) o[d] *= c;
        // pass 2: exp + PV accumulate
        #pragma unroll 2
        for (int j = 0; j < 64; j++) {
            float p = __expf(Ss[j][t] - mnew);
            l += p;
            #pragma unroll
            for (int d = 0; d < 64; d++)
                o[d] = fmaf(p, Vs[j][d], o[d]);
        }
        mrun = mnew;
        __syncthreads();
    }

    float inv = 1.f / l;
    float* op = att + ((long)(b * S_ + srow)) * H_ + h * DH_;   // [B,S,H] layout
    #pragma unroll
    for (int d = 0; d < 64; d += 4) {
        float4 ov = make_float4(o[d] * inv, o[d + 1] * inv, o[d + 2] * inv, o[d + 3] * inv);
        *(float4*)(op + d) = ov;
    }
}

// ---------------- launch ----------------
extern "C" void kernel_launch(void* const* d_in, const int* in_sizes, int n_in,
                              void* d_out, int out_size)
{
    const float* x     = (const float*)d_in[0];
    const float* abias = (const float*)d_in[1];
    const int*   gmask = (const int*)  d_in[2];
    const float* ln1g  = (const float*)d_in[3];
    const float* ln1b  = (const float*)d_in[4];
    const float* Wq    = (const float*)d_in[5];
    const float* bq    = (const float*)d_in[6];
    const float* Wk    = (const float*)d_in[7];
    const float* bk    = (const float*)d_in[8];
    const float* Wv    = (const float*)d_in[9];
    const float* bv    = (const float*)d_in[10];
    const float* Wo    = (const float*)d_in[11];
    const float* bo    = (const float*)d_in[12];
    const float* ln2g  = (const float*)d_in[13];
    const float* ln2b  = (const float*)d_in[14];
    const float* W1    = (const float*)d_in[15];
    const float* b1    = (const float*)d_in[16];
    const float* W2    = (const float*)d_in[17];
    const float* b2    = (const float*)d_in[18];
    float* out = (float*)d_out;

    float *yb, *qb, *kb, *vb, *ab, *x1b, *h1b;
    cudaGetSymbolAddress((void**)&yb,  g_y);
    cudaGetSymbolAddress((void**)&qb,  g_q);
    cudaGetSymbolAddress((void**)&kb,  g_k);
    cudaGetSymbolAddress((void**)&vb,  g_v);
    cudaGetSymbolAddress((void**)&ab,  g_att);
    cudaGetSymbolAddress((void**)&x1b, g_x1);
    cudaGetSymbolAddress((void**)&h1b, g_h1);

    dim3 gH(H_ / 128, M_ / 128);        // (4, 64)
    dim3 gF(FFN_ / 128, M_ / 128);      // (16, 64)

    // 1. LN1
    ln_kernel<<<M_, 256>>>(x, ln1g, ln1b, yb);
    // 2. Q/K/V projections with head scatter
    gemm_kernel<0><<<gH, 256>>>(yb, Wq, bq, nullptr, qb, M_, H_, H_);
    gemm_kernel<0><<<gH, 256>>>(yb, Wk, bk, nullptr, kb, M_, H_, H_);
    gemm_kernel<0><<<gH, 256>>>(yb, Wv, bv, nullptr, vb, M_, H_, H_);
    // 3. flash attention (head = fastest grid dim -> bias/mask L2 reuse across heads)
    attn_kernel<<<dim3(NH_, S_ / 64, B_), 64>>>(qb, kb, vb, abias, gmask, ab);
    // 4. O projection + residual (x)
    gemm_kernel<1><<<gH, 256>>>(ab, Wo, bo, x, x1b, M_, H_, H_);
    // 5. LN2
    ln_kernel<<<M_, 256>>>(x1b, ln2g, ln2b, yb);
    // 6. FFN1 + exact GELU
    gemm_kernel<2><<<gF, 256>>>(yb, W1, b1, nullptr, h1b, M_, FFN_, H_);
    // 7. FFN2 + residual (x1) -> final output
    gemm_kernel<1><<<gH, 256>>>(h1b, W2, b2, x1b, out, M_, H_, FFN_);
}

// round 2
// speedup vs baseline: 1.5425x; 1.5425x over previous
#include <cuda_runtime.h>
#include <math.h>
#include <stdint.h>

#define B_   8
#define S_   1024
#define H_   512
#define NH_  8
#define DH_  64
#define FFN_ 2048
#define M_   (B_*S_)

// ---------------- scratch (device globals; no allocation allowed) ----------------
__device__ float g_y  [M_*H_];
__device__ float g_q  [M_*H_];
__device__ float g_k  [M_*H_];
__device__ float g_v  [M_*H_];
__device__ float g_att[M_*H_];
__device__ float g_x1 [M_*H_];
__device__ float g_h1 [M_*FFN_];
// tf32-rounded weight copies
__device__ float g_wq [H_*H_];
__device__ float g_wk [H_*H_];
__device__ float g_wv [H_*H_];
__device__ float g_wo [H_*H_];
__device__ float g_w1 [H_*FFN_];
__device__ float g_w2 [FFN_*H_];

__device__ __forceinline__ float to_tf32(float x) {
    float r;
    asm("cvt.rna.tf32.f32 %0, %1;" : "=f"(r) : "f"(x));
    return r;
}

// ---------------- weight rounding: fp32 -> tf32-rounded fp32 ----------------
__global__ __launch_bounds__(256) void cvt_kernel(const float* __restrict__ in,
                                                  float* __restrict__ out, int n)
{
    int i = blockIdx.x * 256 + threadIdx.x;
    if (i < n) out[i] = to_tf32(in[i]);
}

// ---------------- LayerNorm: one row (H=512) per 256-thread block ----------------
// Output is tf32-rounded (it only feeds tensor-core GEMMs).
__global__ __launch_bounds__(256) void ln_kernel(
    const float* __restrict__ x, const float* __restrict__ gam,
    const float* __restrict__ bet, float* __restrict__ y)
{
    int row = blockIdx.x;
    int t   = threadIdx.x;
    const float* xr = x + (long)row * H_;
    float a = xr[t];
    float b = xr[t + 256];
    float s = a + b;
    float q = a * a + b * b;
    #pragma unroll
    for (int off = 16; off > 0; off >>= 1) {
        s += __shfl_xor_sync(0xffffffffu, s, off);
        q += __shfl_xor_sync(0xffffffffu, q, off);
    }
    __shared__ float ss[8], qq[8];
    int w = t >> 5, lane = t & 31;
    if (lane == 0) { ss[w] = s; qq[w] = q; }
    __syncthreads();
    float S = 0.f, Q = 0.f;
    #pragma unroll
    for (int i = 0; i < 8; i++) { S += ss[i]; Q += qq[i]; }
    float mean = S * (1.f / H_);
    float var  = Q * (1.f / H_) - mean * mean;
    float inv  = rsqrtf(var + 1e-5f);
    float* yr = y + (long)row * H_;
    yr[t]       = to_tf32((a - mean) * inv * gam[t]       + bet[t]);
    yr[t + 256] = to_tf32((b - mean) * inv * gam[t + 256] + bet[t + 256]);
}

// ---------------- tf32 tensor-core GEMM: C = A[M,K] @ W[K,N] ----------------
// Inputs must already be tf32-rounded. 128x128 CTA tile, BK=16 double-buffered,
// 256 threads = 2x4 warps, warp tile 64x32, mma.sync.m16n8k8.tf32.
// MODE 0: QKV scatter   MODE 1: residual+bias   MODE 2: GELU (tf32-rounded out)
template<int MODE>
__global__ __launch_bounds__(256) void gemm_tc(
    const float* __restrict__ A, const float* __restrict__ Bm,
    const float* __restrict__ bias, const float* __restrict__ res,
    float* __restrict__ Cout, int Md, int Nd, int Kd)
{
    __shared__ float As[2][128 * 20];   // [m][k] stride 20: frag loads conflict-free
    __shared__ float Bs[2][16 * 136];   // [k][n] stride 136: frag loads conflict-free

    const int tid = threadIdx.x;
    const int w   = tid >> 5;
    const int l   = tid & 31;
    const int wm  = w >> 2;             // 0..1
    const int wn  = w & 3;              // 0..3
    const int g   = l >> 2;             // 0..7
    const int tig = l & 3;              // 0..3
    const int c4  = l & 3;              // A-load col group
    const int lr  = l >> 2;             // A-load row-in-warp

    const int bx = blockIdx.x, by = blockIdx.y;
    const float* Ab = A  + (long)(by * 128) * Kd;
    const float* Bb = Bm + bx * 128;

    float acc[4][4][4];
    #pragma unroll
    for (int i = 0; i < 4; i++)
        #pragma unroll
        for (int j = 0; j < 4; j++)
            #pragma unroll
            for (int r = 0; r < 4; r++) acc[i][j][r] = 0.f;

    const int nK = Kd >> 4;

    // ---- prologue: load tile 0 ----
    float4 av0, av1, bv0, bv1;
    {
        const int m0 = w * 8 + lr;
        av0 = *(const float4*)(Ab + (long)m0        * Kd + c4 * 4);
        av1 = *(const float4*)(Ab + (long)(m0 + 64) * Kd + c4 * 4);
        bv0 = *(const float4*)(Bb + (long)w       * Nd + l * 4);
        bv1 = *(const float4*)(Bb + (long)(w + 8) * Nd + l * 4);
        *(float4*)&As[0][(w * 8 + lr)      * 20 + c4 * 4] = av0;
        *(float4*)&As[0][(w * 8 + lr + 64) * 20 + c4 * 4] = av1;
        *(float4*)&Bs[0][ w      * 136 + l * 4] = bv0;
        *(float4*)&Bs[0][(w + 8) * 136 + l * 4] = bv1;
    }
    __syncthreads();

    for (int kt = 0; kt < nK; kt++) {
        const int cur = kt & 1;
        // prefetch next tile into registers
        if (kt + 1 < nK) {
            const int k0g = (kt + 1) * 16;
            const int m0 = w * 8 + lr;
            av0 = *(const float4*)(Ab + (long)m0        * Kd + k0g + c4 * 4);
            av1 = *(const float4*)(Ab + (long)(m0 + 64) * Kd + k0g + c4 * 4);
            bv0 = *(const float4*)(Bb + (long)(k0g + w)     * Nd + l * 4);
            bv1 = *(const float4*)(Bb + (long)(k0g + w + 8) * Nd + l * 4);
        }

        // compute: 2 k-chunks of 8
        const float* Asb = &As[cur][0];
        const float* Bsb = &Bs[cur][0];
        #pragma unroll
        for (int k0 = 0; k0 < 16; k0 += 8) {
            uint32_t af[4][4], bf[4][2];
            #pragma unroll
            for (int mt = 0; mt < 4; mt++) {
                int row = wm * 64 + mt * 16 + g;
                af[mt][0] = __float_as_uint(Asb[ row      * 20 + k0 + tig    ]);
                af[mt][1] = __float_as_uint(Asb[(row + 8) * 20 + k0 + tig    ]);
                af[mt][2] = __float_as_uint(Asb[ row      * 20 + k0 + tig + 4]);
                af[mt][3] = __float_as_uint(Asb[(row + 8) * 20 + k0 + tig + 4]);
            }
            #pragma unroll
            for (int nt = 0; nt < 4; nt++) {
                int col = wn * 32 + nt * 8 + g;
                bf[nt][0] = __float_as_uint(Bsb[(k0 + tig)     * 136 + col]);
                bf[nt][1] = __float_as_uint(Bsb[(k0 + tig + 4) * 136 + col]);
            }
            #pragma unroll
            for (int mt = 0; mt < 4; mt++)
                #pragma unroll
                for (int nt = 0; nt < 4; nt++) {
                    float* c = acc[mt][nt];
                    asm("mma.sync.aligned.m16n8k8.row.col.f32.tf32.tf32.f32 "
                        "{%0,%1,%2,%3}, {%4,%5,%6,%7}, {%8,%9}, {%0,%1,%2,%3};"
                        : "+f"(c[0]), "+f"(c[1]), "+f"(c[2]), "+f"(c[3])
                        : "r"(af[mt][0]), "r"(af[mt][1]), "r"(af[mt][2]), "r"(af[mt][3]),
                          "r"(bf[nt][0]), "r"(bf[nt][1]));
                }
        }

        // stage next tile into the other buffer
        if (kt + 1 < nK) {
            const int nxt = (kt + 1) & 1;
            *(float4*)&As[nxt][(w * 8 + lr)      * 20 + c4 * 4] = av0;
            *(float4*)&As[nxt][(w * 8 + lr + 64) * 20 + c4 * 4] = av1;
            *(float4*)&Bs[nxt][ w      * 136 + l * 4] = bv0;
            *(float4*)&Bs[nxt][(w + 8) * 136 + l * 4] = bv1;
        }
        __syncthreads();
    }

    // ---- epilogue ----
    #pragma unroll
    for (int mt = 0; mt < 4; mt++) {
        #pragma unroll
        for (int half = 0; half < 2; half++) {
            int mr = by * 128 + wm * 64 + mt * 16 + g + half * 8;
            #pragma unroll
            for (int nt = 0; nt < 4; nt++) {
                int nc = bx * 128 + wn * 32 + nt * 8 + 2 * tig;
                float v0 = acc[mt][nt][half * 2 + 0] + bias[nc];
                float v1 = acc[mt][nt][half * 2 + 1] + bias[nc + 1];
                if (MODE == 0) {
                    int b = mr >> 10, s = mr & 1023;
                    int h = nc >> 6,  d = nc & 63;
                    long idx = ((long)((b * NH_ + h) << 10) + s) * DH_ + d;
                    *(float2*)&Cout[idx] = make_float2(v0, v1);
                } else if (MODE == 1) {
                    long idx = (long)mr * Nd + nc;
                    float2 rv = *(const float2*)&res[idx];
                    *(float2*)&Cout[idx] = make_float2(rv.x + v0, rv.y + v1);
                } else {
                    long idx = (long)mr * Nd + nc;
                    float gelu0 = 0.5f * v0 * (1.f + erff(v0 * 0.70710678118f));
                    float gelu1 = 0.5f * v1 * (1.f + erff(v1 * 0.70710678118f));
                    *(float2*)&Cout[idx] = make_float2(to_tf32(gelu0), to_tf32(gelu1));
                }
            }
        }
    }
}

// ---------------- Flash attention: 64 q-rows / block, 64-key tiles ----------------
// Output tf32-rounded (feeds O projection on tensor cores).
__global__ __launch_bounds__(64) void attn_kernel(
    const float* __restrict__ q, const float* __restrict__ k,
    const float* __restrict__ v, const float* __restrict__ bias,
    const int* __restrict__ mask, float* __restrict__ att)
{
    __shared__ float Ks[64][64];
    __shared__ float Vs[64][64];
    __shared__ float Ss[64][64];

    int h = blockIdx.x, qt = blockIdx.y, b = blockIdx.z;
    int t = threadIdx.x;
    int srow = qt * 64 + t;

    const float* qp = q + ((long)((b * NH_ + h) * S_) + srow) * DH_;
    float qr[64];
    #pragma unroll
    for (int d = 0; d < 64; d++) qr[d] = qp[d] * 0.125f;

    float o[64];
    #pragma unroll
    for (int d = 0; d < 64; d++) o[d] = 0.f;
    float mrun = -3.0e38f, l = 0.f;

    const float4* kb = (const float4*)(k + (long)((b * NH_ + h) * S_) * DH_);
    const float4* vb = (const float4*)(v + (long)((b * NH_ + h) * S_) * DH_);
    const float*  brow = bias + ((long)b * S_ + srow) * S_;
    const int*    mrow = mask + ((long)b * S_ + srow) * S_;

    for (int kt = 0; kt < S_ / 64; kt++) {
        float4* kd = (float4*)&Ks[0][0];
        float4* vd = (float4*)&Vs[0][0];
        const float4* ksrc = kb + kt * 64 * 16;
        const float4* vsrc = vb + kt * 64 * 16;
        #pragma unroll
        for (int i = 0; i < 16; i++) {
            kd[t + i * 64] = ksrc[t + i * 64];
            vd[t + i * 64] = vsrc[t + i * 64];
        }
        __syncthreads();

        int kk0 = kt * 64;
        float tmax = -3.0e38f;
        #pragma unroll 2
        for (int j = 0; j < 64; j++) {
            float s0 = 0.f, s1 = 0.f, s2 = 0.f, s3 = 0.f;
            #pragma unroll
            for (int d = 0; d < 64; d += 4) {
                s0 = fmaf(qr[d    ], Ks[j][d    ], s0);
                s1 = fmaf(qr[d + 1], Ks[j][d + 1], s1);
                s2 = fmaf(qr[d + 2], Ks[j][d + 2], s2);
                s3 = fmaf(qr[d + 3], Ks[j][d + 3], s3);
            }
            float s = (s0 + s1) + (s2 + s3);
            float sc = (mrow[kk0 + j] == 0) ? -1e9f : (s + brow[kk0 + j]);
            Ss[j][t] = sc;
            tmax = fmaxf(tmax, sc);
        }
        float mnew = fmaxf(mrun, tmax);
        float c = __expf(mrun - mnew);
        l *= c;
        #pragma unroll
        for (int d = 0; d < 64; d++) o[d] *= c;
        #pragma unroll 2
        for (int j = 0; j < 64; j++) {
            float p = __expf(Ss[j][t] - mnew);
            l += p;
            #pragma unroll
            for (int d = 0; d < 64; d++)
                o[d] = fmaf(p, Vs[j][d], o[d]);
        }
        mrun = mnew;
        __syncthreads();
    }

    float inv = 1.f / l;
    float* op = att + ((long)(b * S_ + srow)) * H_ + h * DH_;
    #pragma unroll
    for (int d = 0; d < 64; d += 4) {
        float4 ov = make_float4(to_tf32(o[d] * inv), to_tf32(o[d + 1] * inv),
                                to_tf32(o[d + 2] * inv), to_tf32(o[d + 3] * inv));
        *(float4*)(op + d) = ov;
    }
}

// ---------------- launch ----------------
extern "C" void kernel_launch(void* const* d_in, const int* in_sizes, int n_in,
                              void* d_out, int out_size)
{
    const float* x     = (const float*)d_in[0];
    const float* abias = (const float*)d_in[1];
    const int*   gmask = (const int*)  d_in[2];
    const float* ln1g  = (const float*)d_in[3];
    const float* ln1b  = (const float*)d_in[4];
    const float* Wq    = (const float*)d_in[5];
    const float* bq    = (const float*)d_in[6];
    const float* Wk    = (const float*)d_in[7];
    const float* bk    = (const float*)d_in[8];
    const float* Wv    = (const float*)d_in[9];
    const float* bv    = (const float*)d_in[10];
    const float* Wo    = (const float*)d_in[11];
    const float* bo    = (const float*)d_in[12];
    const float* ln2g  = (const float*)d_in[13];
    const float* ln2b  = (const float*)d_in[14];
    const float* W1    = (const float*)d_in[15];
    const float* b1    = (const float*)d_in[16];
    const float* W2    = (const float*)d_in[17];
    const float* b2    = (const float*)d_in[18];
    float* out = (float*)d_out;

    float *yb, *qb, *kb, *vb, *ab, *x1b, *h1b;
    float *wq, *wk, *wv, *wo, *w1, *w2;
    cudaGetSymbolAddress((void**)&yb,  g_y);
    cudaGetSymbolAddress((void**)&qb,  g_q);
    cudaGetSymbolAddress((void**)&kb,  g_k);
    cudaGetSymbolAddress((void**)&vb,  g_v);
    cudaGetSymbolAddress((void**)&ab,  g_att);
    cudaGetSymbolAddress((void**)&x1b, g_x1);
    cudaGetSymbolAddress((void**)&h1b, g_h1);
    cudaGetSymbolAddress((void**)&wq,  g_wq);
    cudaGetSymbolAddress((void**)&wk,  g_wk);
    cudaGetSymbolAddress((void**)&wv,  g_wv);
    cudaGetSymbolAddress((void**)&wo,  g_wo);
    cudaGetSymbolAddress((void**)&w1,  g_w1);
    cudaGetSymbolAddress((void**)&w2,  g_w2);

    // round weights to tf32 once per launch (cheap, ~12MB)
    cvt_kernel<<<(H_*H_   + 255)/256, 256>>>(Wq, wq, H_*H_);
    cvt_kernel<<<(H_*H_   + 255)/256, 256>>>(Wk, wk, H_*H_);
    cvt_kernel<<<(H_*H_   + 255)/256, 256>>>(Wv, wv, H_*H_);
    cvt_kernel<<<(H_*H_   + 255)/256, 256>>>(Wo, wo, H_*H_);
    cvt_kernel<<<(H_*FFN_ + 255)/256, 256>>>(W1, w1, H_*FFN_);
    cvt_kernel<<<(FFN_*H_ + 255)/256, 256>>>(W2, w2, FFN_*H_);

    dim3 gH(H_ / 128, M_ / 128);        // (4, 64)
    dim3 gF(FFN_ / 128, M_ / 128);      // (16, 64)

    ln_kernel<<<M_, 256>>>(x, ln1g, ln1b, yb);
    gemm_tc<0><<<gH, 256>>>(yb, wq, bq, nullptr, qb, M_, H_, H_);
    gemm_tc<0><<<gH, 256>>>(yb, wk, bk, nullptr, kb, M_, H_, H_);
    gemm_tc<0><<<gH, 256>>>(yb, wv, bv, nullptr, vb, M_, H_, H_);
    attn_kernel<<<dim3(NH_, S_ / 64, B_), 64>>>(qb, kb, vb, abias, gmask, ab);
    gemm_tc<1><<<gH, 256>>>(ab, wo, bo, x, x1b, M_, H_, H_);
    ln_kernel<<<M_, 256>>>(x1b, ln2g, ln2b, yb);
    gemm_tc<2><<<gF, 256>>>(yb, w1, b1, nullptr, h1b, M_, FFN_, H_);
    gemm_tc<1><<<gH, 256>>>(h1b, w2, b2, x1b, out, M_, H_, FFN_);
}

// round 3
// speedup vs baseline: 2.4195x; 1.5685x over previous
#include <cuda_runtime.h>
#include <math.h>
#include <stdint.h>

#define B_   8
#define S_   1024
#define H_   512
#define NH_  8
#define DH_  64
#define FFN_ 2048
#define M_   (B_*S_)

// ---------------- scratch (device globals; no allocation allowed) ----------------
__device__ float g_y  [M_*H_];
__device__ float g_q  [M_*H_];
__device__ float g_k  [M_*H_];
__device__ float g_v  [M_*H_];
__device__ float g_att[M_*H_];
__device__ float g_x1 [M_*H_];
__device__ float g_h1 [M_*FFN_];
// tf32-rounded weight copies
__device__ float g_wq [H_*H_];
__device__ float g_wk [H_*H_];
__device__ float g_wv [H_*H_];
__device__ float g_wo [H_*H_];
__device__ float g_w1 [H_*FFN_];
__device__ float g_w2 [FFN_*H_];

__device__ __forceinline__ float to_tf32(float x) {
    float r;
    asm("cvt.rna.tf32.f32 %0, %1;" : "=f"(r) : "f"(x));
    return r;
}

__device__ __forceinline__ void mma_tf32(float* c, const uint32_t* a,
                                         uint32_t b0, uint32_t b1) {
    asm("mma.sync.aligned.m16n8k8.row.col.f32.tf32.tf32.f32 "
        "{%0,%1,%2,%3}, {%4,%5,%6,%7}, {%8,%9}, {%0,%1,%2,%3};"
        : "+f"(c[0]), "+f"(c[1]), "+f"(c[2]), "+f"(c[3])
        : "r"(a[0]), "r"(a[1]), "r"(a[2]), "r"(a[3]), "r"(b0), "r"(b1));
}

// ---------------- weight rounding: fp32 -> tf32-rounded fp32 ----------------
__global__ __launch_bounds__(256) void cvt_kernel(const float* __restrict__ in,
                                                  float* __restrict__ out, int n)
{
    int i = blockIdx.x * 256 + threadIdx.x;
    if (i < n) out[i] = to_tf32(in[i]);
}

// ---------------- LayerNorm: one row (H=512) per 256-thread block ----------------
__global__ __launch_bounds__(256) void ln_kernel(
    const float* __restrict__ x, const float* __restrict__ gam,
    const float* __restrict__ bet, float* __restrict__ y)
{
    int row = blockIdx.x;
    int t   = threadIdx.x;
    const float* xr = x + (long)row * H_;
    float a = xr[t];
    float b = xr[t + 256];
    float s = a + b;
    float q = a * a + b * b;
    #pragma unroll
    for (int off = 16; off > 0; off >>= 1) {
        s += __shfl_xor_sync(0xffffffffu, s, off);
        q += __shfl_xor_sync(0xffffffffu, q, off);
    }
    __shared__ float ss[8], qq[8];
    int w = t >> 5, lane = t & 31;
    if (lane == 0) { ss[w] = s; qq[w] = q; }
    __syncthreads();
    float S = 0.f, Q = 0.f;
    #pragma unroll
    for (int i = 0; i < 8; i++) { S += ss[i]; Q += qq[i]; }
    float mean = S * (1.f / H_);
    float var  = Q * (1.f / H_) - mean * mean;
    float inv  = rsqrtf(var + 1e-5f);
    float* yr = y + (long)row * H_;
    yr[t]       = to_tf32((a - mean) * inv * gam[t]       + bet[t]);
    yr[t + 256] = to_tf32((b - mean) * inv * gam[t + 256] + bet[t + 256]);
}

// ---------------- tf32 tensor-core GEMM (unchanged from round 2) ----------------
template<int MODE>
__global__ __launch_bounds__(256) void gemm_tc(
    const float* __restrict__ A, const float* __restrict__ Bm,
    const float* __restrict__ bias, const float* __restrict__ res,
    float* __restrict__ Cout, int Md, int Nd, int Kd)
{
    __shared__ float As[2][128 * 20];
    __shared__ float Bs[2][16 * 136];

    const int tid = threadIdx.x;
    const int w   = tid >> 5;
    const int l   = tid & 31;
    const int wm  = w >> 2;
    const int wn  = w & 3;
    const int g   = l >> 2;
    const int tig = l & 3;
    const int c4  = l & 3;
    const int lr  = l >> 2;

    const int bx = blockIdx.x, by = blockIdx.y;
    const float* Ab = A  + (long)(by * 128) * Kd;
    const float* Bb = Bm + bx * 128;

    float acc[4][4][4];
    #pragma unroll
    for (int i = 0; i < 4; i++)
        #pragma unroll
        for (int j = 0; j < 4; j++)
            #pragma unroll
            for (int r = 0; r < 4; r++) acc[i][j][r] = 0.f;

    const int nK = Kd >> 4;

    float4 av0, av1, bv0, bv1;
    {
        const int m0 = w * 8 + lr;
        av0 = *(const float4*)(Ab + (long)m0        * Kd + c4 * 4);
        av1 = *(const float4*)(Ab + (long)(m0 + 64) * Kd + c4 * 4);
        bv0 = *(const float4*)(Bb + (long)w       * Nd + l * 4);
        bv1 = *(const float4*)(Bb + (long)(w + 8) * Nd + l * 4);
        *(float4*)&As[0][(w * 8 + lr)      * 20 + c4 * 4] = av0;
        *(float4*)&As[0][(w * 8 + lr + 64) * 20 + c4 * 4] = av1;
        *(float4*)&Bs[0][ w      * 136 + l * 4] = bv0;
        *(float4*)&Bs[0][(w + 8) * 136 + l * 4] = bv1;
    }
    __syncthreads();

    for (int kt = 0; kt < nK; kt++) {
        const int cur = kt & 1;
        if (kt + 1 < nK) {
            const int k0g = (kt + 1) * 16;
            const int m0 = w * 8 + lr;
            av0 = *(const float4*)(Ab + (long)m0        * Kd + k0g + c4 * 4);
            av1 = *(const float4*)(Ab + (long)(m0 + 64) * Kd + k0g + c4 * 4);
            bv0 = *(const float4*)(Bb + (long)(k0g + w)     * Nd + l * 4);
            bv1 = *(const float4*)(Bb + (long)(k0g + w + 8) * Nd + l * 4);
        }

        const float* Asb = &As[cur][0];
        const float* Bsb = &Bs[cur][0];
        #pragma unroll
        for (int k0 = 0; k0 < 16; k0 += 8) {
            uint32_t af[4][4], bf[4][2];
            #pragma unroll
            for (int mt = 0; mt < 4; mt++) {
                int row = wm * 64 + mt * 16 + g;
                af[mt][0] = __float_as_uint(Asb[ row      * 20 + k0 + tig    ]);
                af[mt][1] = __float_as_uint(Asb[(row + 8) * 20 + k0 + tig    ]);
                af[mt][2] = __float_as_uint(Asb[ row      * 20 + k0 + tig + 4]);
                af[mt][3] = __float_as_uint(Asb[(row + 8) * 20 + k0 + tig + 4]);
            }
            #pragma unroll
            for (int nt = 0; nt < 4; nt++) {
                int col = wn * 32 + nt * 8 + g;
                bf[nt][0] = __float_as_uint(Bsb[(k0 + tig)     * 136 + col]);
                bf[nt][1] = __float_as_uint(Bsb[(k0 + tig + 4) * 136 + col]);
            }
            #pragma unroll
            for (int mt = 0; mt < 4; mt++)
                #pragma unroll
                for (int nt = 0; nt < 4; nt++)
                    mma_tf32(acc[mt][nt], af[mt], bf[nt][0], bf[nt][1]);
        }

        if (kt + 1 < nK) {
            const int nxt = (kt + 1) & 1;
            *(float4*)&As[nxt][(w * 8 + lr)      * 20 + c4 * 4] = av0;
            *(float4*)&As[nxt][(w * 8 + lr + 64) * 20 + c4 * 4] = av1;
            *(float4*)&Bs[nxt][ w      * 136 + l * 4] = bv0;
            *(float4*)&Bs[nxt][(w + 8) * 136 + l * 4] = bv1;
        }
        __syncthreads();
    }

    #pragma unroll
    for (int mt = 0; mt < 4; mt++) {
        #pragma unroll
        for (int half = 0; half < 2; half++) {
            int mr = by * 128 + wm * 64 + mt * 16 + g + half * 8;
            #pragma unroll
            for (int nt = 0; nt < 4; nt++) {
                int nc = bx * 128 + wn * 32 + nt * 8 + 2 * tig;
                float v0 = acc[mt][nt][half * 2 + 0] + bias[nc];
                float v1 = acc[mt][nt][half * 2 + 1] + bias[nc + 1];
                if (MODE == 0) {
                    int b = mr >> 10, s = mr & 1023;
                    int h = nc >> 6,  d = nc & 63;
                    long idx = ((long)((b * NH_ + h) << 10) + s) * DH_ + d;
                    *(float2*)&Cout[idx] = make_float2(v0, v1);
                } else if (MODE == 1) {
                    long idx = (long)mr * Nd + nc;
                    float2 rv = *(const float2*)&res[idx];
                    *(float2*)&Cout[idx] = make_float2(rv.x + v0, rv.y + v1);
                } else {
                    long idx = (long)mr * Nd + nc;
                    float gelu0 = 0.5f * v0 * (1.f + erff(v0 * 0.70710678118f));
                    float gelu1 = 0.5f * v1 * (1.f + erff(v1 * 0.70710678118f));
                    *(float2*)&Cout[idx] = make_float2(to_tf32(gelu0), to_tf32(gelu1));
                }
            }
        }
    }
}

// ---------------- Tensor-core flash attention ----------------
// 128 threads = 4 warps. CTA = 64 q-rows; warp w owns rows [w*16, w*16+16).
// Key loop in tiles of 64. QK^T and P.V via mma.m16n8k8.tf32.
// SMEM: Qs/Ps [64][68] (aliased), Ks [d=64][65] (transposed), Vs [key=64][66].
__global__ __launch_bounds__(128) void attn_tc(
    const float* __restrict__ q, const float* __restrict__ k,
    const float* __restrict__ v, const float* __restrict__ bias,
    const int* __restrict__ mask, float* __restrict__ att)
{
    extern __shared__ float sm[];
    float* Qs = sm;                     // [64][68], later reused as Ps
    float* Ks = sm + 64 * 68;           // [64][65]  indexed [d][key]
    float* Vs = Ks + 64 * 65;           // [64][66]  indexed [key][d]

    const int h = blockIdx.x, qt = blockIdx.y, b = blockIdx.z;
    const int tid = threadIdx.x;
    const int w = tid >> 5, l = tid & 31;
    const int g = l >> 2, tig = l & 3;

    const long headoff = (long)((b * NH_ + h) * S_) * DH_;
    const float* qg = q + headoff + (long)qt * 64 * DH_;
    const float* kg = k + headoff;
    const float* vg = v + headoff;

    // ---- stage Q (pre-scaled, tf32) ----
    #pragma unroll
    for (int j = 0; j < 16; j++) {
        int lin = tid + j * 128;                 // 0..2047
        int r = lin >> 5, c2 = (lin & 31) * 2;
        float2 qv = *(const float2*)(qg + r * 64 + c2);
        Qs[r * 68 + c2]     = to_tf32(qv.x * 0.125f);
        Qs[r * 68 + c2 + 1] = to_tf32(qv.y * 0.125f);
    }
    __syncthreads();

    const int qrow = w * 16 + g;                 // warp-local A-frag row
    uint32_t qf[8][4];
    #pragma unroll
    for (int kk = 0; kk < 8; kk++) {
        qf[kk][0] = __float_as_uint(Qs[ qrow      * 68 + kk * 8 + tig    ]);
        qf[kk][1] = __float_as_uint(Qs[(qrow + 8) * 68 + kk * 8 + tig    ]);
        qf[kk][2] = __float_as_uint(Qs[ qrow      * 68 + kk * 8 + tig + 4]);
        qf[kk][3] = __float_as_uint(Qs[(qrow + 8) * 68 + kk * 8 + tig + 4]);
    }
    __syncthreads();                             // Qs free -> becomes Ps

    float of[8][4];
    #pragma unroll
    for (int nt = 0; nt < 8; nt++)
        #pragma unroll
        for (int r = 0; r < 4; r++) of[nt][r] = 0.f;
    float m0 = -3.0e38f, m1 = -3.0e38f, l0 = 0.f, l1 = 0.f;

    const long srow0 = (long)b * S_ + qt * 64 + w * 16 + g;
    const float* brow0 = bias + srow0 * S_;
    const float* brow1 = brow0 + 8L * S_;
    const int*   mrow0 = mask + srow0 * S_;
    const int*   mrow1 = mrow0 + 8L * S_;

    float* Ps = Qs;

    for (int kt = 0; kt < S_ / 64; kt++) {
        // ---- load K (transposed) + V tiles ----
        #pragma unroll
        for (int j = 0; j < 16; j++) {
            int lin = tid + j * 128;
            int r = lin >> 5, c2 = (lin & 31) * 2;
            float2 kv = *(const float2*)(kg + (long)(kt * 64 + r) * 64 + c2);
            Ks[(c2    ) * 65 + r] = to_tf32(kv.x);
            Ks[(c2 + 1) * 65 + r] = to_tf32(kv.y);
            float2 vv = *(const float2*)(vg + (long)(kt * 64 + r) * 64 + c2);
            *(float2*)&Vs[r * 66 + c2] = make_float2(to_tf32(vv.x), to_tf32(vv.y));
        }
        __syncthreads();

        // ---- S = Q K^T ----
        float sacc[8][4];
        #pragma unroll
        for (int nt = 0; nt < 8; nt++)
            #pragma unroll
            for (int r = 0; r < 4; r++) sacc[nt][r] = 0.f;
        #pragma unroll
        for (int kk = 0; kk < 8; kk++) {
            #pragma unroll
            for (int nt = 0; nt < 8; nt++) {
                uint32_t b0 = __float_as_uint(Ks[(kk * 8 + tig    ) * 65 + nt * 8 + g]);
                uint32_t b1 = __float_as_uint(Ks[(kk * 8 + tig + 4) * 65 + nt * 8 + g]);
                mma_tf32(sacc[nt], qf[kk], b0, b1);
            }
        }

        // ---- bias/mask + online softmax ----
        float tmax0 = -3.0e38f, tmax1 = -3.0e38f;
        #pragma unroll
        for (int nt = 0; nt < 8; nt++) {
            int kc = kt * 64 + nt * 8 + 2 * tig;
            float2 bv0 = *(const float2*)(brow0 + kc);
            float2 bv1 = *(const float2*)(brow1 + kc);
            int2   mv0 = *(const int2*)  (mrow0 + kc);
            int2   mv1 = *(const int2*)  (mrow1 + kc);
            sacc[nt][0] = mv0.x ? sacc[nt][0] + bv0.x : -1e9f;
            sacc[nt][1] = mv0.y ? sacc[nt][1] + bv0.y : -1e9f;
            sacc[nt][2] = mv1.x ? sacc[nt][2] + bv1.x : -1e9f;
            sacc[nt][3] = mv1.y ? sacc[nt][3] + bv1.y : -1e9f;
            tmax0 = fmaxf(tmax0, fmaxf(sacc[nt][0], sacc[nt][1]));
            tmax1 = fmaxf(tmax1, fmaxf(sacc[nt][2], sacc[nt][3]));
        }
        tmax0 = fmaxf(tmax0, __shfl_xor_sync(0xffffffffu, tmax0, 1));
        tmax0 = fmaxf(tmax0, __shfl_xor_sync(0xffffffffu, tmax0, 2));
        tmax1 = fmaxf(tmax1, __shfl_xor_sync(0xffffffffu, tmax1, 1));
        tmax1 = fmaxf(tmax1, __shfl_xor_sync(0xffffffffu, tmax1, 2));
        float mn0 = fmaxf(m0, tmax0), mn1 = fmaxf(m1, tmax1);
        float c0 = __expf(m0 - mn0), c1 = __expf(m1 - mn1);
        l0 *= c0; l1 *= c1;
        m0 = mn0; m1 = mn1;
        #pragma unroll
        for (int nt = 0; nt < 8; nt++) {
            of[nt][0] *= c0; of[nt][1] *= c0;
            of[nt][2] *= c1; of[nt][3] *= c1;
            float p0 = __expf(sacc[nt][0] - m0);
            float p1 = __expf(sacc[nt][1] - m0);
            float p2 = __expf(sacc[nt][2] - m1);
            float p3 = __expf(sacc[nt][3] - m1);
            l0 += p0 + p1; l1 += p2 + p3;
            *(float2*)&Ps[ qrow      * 68 + nt * 8 + 2 * tig] =
                make_float2(to_tf32(p0), to_tf32(p1));
            *(float2*)&Ps[(qrow + 8) * 68 + nt * 8 + 2 * tig] =
                make_float2(to_tf32(p2), to_tf32(p3));
        }
        __syncwarp();

        // ---- O += P V ----
        #pragma unroll
        for (int kk = 0; kk < 8; kk++) {
            uint32_t pf[4];
            pf[0] = __float_as_uint(Ps[ qrow      * 68 + kk * 8 + tig    ]);
            pf[1] = __float_as_uint(Ps[(qrow + 8) * 68 + kk * 8 + tig    ]);
            pf[2] = __float_as_uint(Ps[ qrow      * 68 + kk * 8 + tig + 4]);
            pf[3] = __float_as_uint(Ps[(qrow + 8) * 68 + kk * 8 + tig + 4]);
            #pragma unroll
            for (int nt = 0; nt < 8; nt++) {
                uint32_t b0 = __float_as_uint(Vs[(kk * 8 + tig    ) * 66 + nt * 8 + g]);
                uint32_t b1 = __float_as_uint(Vs[(kk * 8 + tig + 4) * 66 + nt * 8 + g]);
                mma_tf32(of[nt], pf, b0, b1);
            }
        }
        __syncthreads();
    }

    // ---- normalize + write out ([B,S,H] layout, tf32-rounded) ----
    l0 += __shfl_xor_sync(0xffffffffu, l0, 1);
    l0 += __shfl_xor_sync(0xffffffffu, l0, 2);
    l1 += __shfl_xor_sync(0xffffffffu, l1, 1);
    l1 += __shfl_xor_sync(0xffffffffu, l1, 2);
    float inv0 = 1.f / l0, inv1 = 1.f / l1;

    const long orow0 = (long)b * S_ + qt * 64 + w * 16 + g;
    #pragma unroll
    for (int nt = 0; nt < 8; nt++) {
        int col = h * 64 + nt * 8 + 2 * tig;
        *(float2*)&att[ orow0      * H_ + col] =
            make_float2(to_tf32(of[nt][0] * inv0), to_tf32(of[nt][1] * inv0));
        *(float2*)&att[(orow0 + 8) * H_ + col] =
            make_float2(to_tf32(of[nt][2] * inv1), to_tf32(of[nt][3] * inv1));
    }
}

// ---------------- launch ----------------
extern "C" void kernel_launch(void* const* d_in, const int* in_sizes, int n_in,
                              void* d_out, int out_size)
{
    const float* x     = (const float*)d_in[0];
    const float* abias = (const float*)d_in[1];
    const int*   gmask = (const int*)  d_in[2];
    const float* ln1g  = (const float*)d_in[3];
    const float* ln1b  = (const float*)d_in[4];
    const float* Wq    = (const float*)d_in[5];
    const float* bq    = (const float*)d_in[6];
    const float* Wk    = (const float*)d_in[7];
    const float* bk    = (const float*)d_in[8];
    const float* Wv    = (const float*)d_in[9];
    const float* bv    = (const float*)d_in[10];
    const float* Wo    = (const float*)d_in[11];
    const float* bo    = (const float*)d_in[12];
    const float* ln2g  = (const float*)d_in[13];
    const float* ln2b  = (const float*)d_in[14];
    const float* W1    = (const float*)d_in[15];
    const float* b1    = (const float*)d_in[16];
    const float* W2    = (const float*)d_in[17];
    const float* b2    = (const float*)d_in[18];
    float* out = (float*)d_out;

    float *yb, *qb, *kb, *vb, *ab, *x1b, *h1b;
    float *wq, *wk, *wv, *wo, *w1, *w2;
    cudaGetSymbolAddress((void**)&yb,  g_y);
    cudaGetSymbolAddress((void**)&qb,  g_q);
    cudaGetSymbolAddress((void**)&kb,  g_k);
    cudaGetSymbolAddress((void**)&vb,  g_v);
    cudaGetSymbolAddress((void**)&ab,  g_att);
    cudaGetSymbolAddress((void**)&x1b, g_x1);
    cudaGetSymbolAddress((void**)&h1b, g_h1);
    cudaGetSymbolAddress((void**)&wq,  g_wq);
    cudaGetSymbolAddress((void**)&wk,  g_wk);
    cudaGetSymbolAddress((void**)&wv,  g_wv);
    cudaGetSymbolAddress((void**)&wo,  g_wo);
    cudaGetSymbolAddress((void**)&w1,  g_w1);
    cudaGetSymbolAddress((void**)&w2,  g_w2);

    static int smem_set = 0;
    const int ATTN_SMEM = (64 * 68 + 64 * 65 + 64 * 66) * 4;   // 50944 B
    if (!smem_set) {
        cudaFuncSetAttribute(attn_tc, cudaFuncAttributeMaxDynamicSharedMemorySize,
                             ATTN_SMEM);
        smem_set = 1;
    }

    cvt_kernel<<<(H_*H_   + 255)/256, 256>>>(Wq, wq, H_*H_);
    cvt_kernel<<<(H_*H_   + 255)/256, 256>>>(Wk, wk, H_*H_);
    cvt_kernel<<<(H_*H_   + 255)/256, 256>>>(Wv, wv, H_*H_);
    cvt_kernel<<<(H_*H_   + 255)/256, 256>>>(Wo, wo, H_*H_);
    cvt_kernel<<<(H_*FFN_ + 255)/256, 256>>>(W1, w1, H_*FFN_);
    cvt_kernel<<<(FFN_*H_ + 255)/256, 256>>>(W2, w2, FFN_*H_);

    dim3 gH(H_ / 128, M_ / 128);        // (4, 64)
    dim3 gF(FFN_ / 128, M_ / 128);      // (16, 64)

    ln_kernel<<<M_, 256>>>(x, ln1g, ln1b, yb);
    gemm_tc<0><<<gH, 256>>>(yb, wq, bq, nullptr, qb, M_, H_, H_);
    gemm_tc<0><<<gH, 256>>>(yb, wk, bk, nullptr, kb, M_, H_, H_);
    gemm_tc<0><<<gH, 256>>>(yb, wv, bv, nullptr, vb, M_, H_, H_);
    attn_tc<<<dim3(NH_, S_ / 64, B_), 128, ATTN_SMEM>>>(qb, kb, vb, abias, gmask, ab);
    gemm_tc<1><<<gH, 256>>>(ab, wo, bo, x, x1b, M_, H_, H_);
    ln_kernel<<<M_, 256>>>(x1b, ln2g, ln2b, yb);
    gemm_tc<2><<<gF, 256>>>(yb, w1, b1, nullptr, h1b, M_, FFN_, H_);
    gemm_tc<1><<<gH, 256>>>(h1b, w2, b2, x1b, out, M_, H_, FFN_);
}

// round 4
// speedup vs baseline: 2.6158x; 1.0811x over previous
#include <cuda_runtime.h>
#include <math.h>
#include <stdint.h>

#define B_   8
#define S_   1024
#define H_   512
#define NH_  8
#define DH_  64
#define FFN_ 2048
#define M_   (B_*S_)

// ---------------- scratch (device globals; no allocation allowed) ----------------
__device__ float g_y  [M_*H_];
__device__ float g_q  [M_*H_];
__device__ float g_k  [M_*H_];
__device__ float g_v  [M_*H_];
__device__ float g_att[M_*H_];
__device__ float g_x1 [M_*H_];
__device__ float g_h1 [M_*FFN_];
// tf32-rounded weights
__device__ float g_wqkv[H_*3*H_];
__device__ float g_bqkv[3*H_];
__device__ float g_wo [H_*H_];
__device__ float g_w1 [H_*FFN_];
__device__ float g_w2 [FFN_*H_];

__device__ __forceinline__ float to_tf32(float x) {
    float r;
    asm("cvt.rna.tf32.f32 %0, %1;" : "=f"(r) : "f"(x));
    return r;
}

__device__ __forceinline__ void mma_tf32(float* c, const uint32_t* a,
                                         uint32_t b0, uint32_t b1) {
    asm("mma.sync.aligned.m16n8k8.row.col.f32.tf32.tf32.f32 "
        "{%0,%1,%2,%3}, {%4,%5,%6,%7}, {%8,%9}, {%0,%1,%2,%3};"
        : "+f"(c[0]), "+f"(c[1]), "+f"(c[2]), "+f"(c[3])
        : "r"(a[0]), "r"(a[1]), "r"(a[2]), "r"(a[3]), "r"(b0), "r"(b1));
}

__device__ __forceinline__ void cp_async16(uint32_t smem_dst, const void* gsrc) {
    asm volatile("cp.async.cg.shared.global [%0], [%1], 16;"
                 :: "r"(smem_dst), "l"(gsrc));
}
__device__ __forceinline__ void cp_commit() {
    asm volatile("cp.async.commit_group;");
}
template<int N>
__device__ __forceinline__ void cp_wait() {
    asm volatile("cp.async.wait_group %0;" :: "n"(N));
}

// ---------------- weight prep ----------------
__global__ __launch_bounds__(256) void cvt_kernel(const float* __restrict__ in,
                                                  float* __restrict__ out, int n)
{
    int i = blockIdx.x * 256 + threadIdx.x;
    if (i < n) out[i] = to_tf32(in[i]);
}

// pack Wq|Wk|Wv side by side into [K=512][N=1536], tf32-rounded
__global__ __launch_bounds__(256) void cvt_qkv_kernel(
    const float* __restrict__ wq, const float* __restrict__ wk,
    const float* __restrict__ wv, float* __restrict__ out)
{
    int i = blockIdx.x * 256 + threadIdx.x;
    if (i < H_ * H_) {
        int k = i >> 9, n = i & 511;
        out[k * 1536 + n]        = to_tf32(wq[i]);
        out[k * 1536 + 512 + n]  = to_tf32(wk[i]);
        out[k * 1536 + 1024 + n] = to_tf32(wv[i]);
    }
}

__global__ __launch_bounds__(256) void cat_bias_kernel(
    const float* __restrict__ a, const float* __restrict__ b,
    const float* __restrict__ c, float* __restrict__ o)
{
    int i = blockIdx.x * 256 + threadIdx.x;
    if (i < 512) { o[i] = a[i]; o[i + 512] = b[i]; o[i + 1024] = c[i]; }
}

// ---------------- LayerNorm ----------------
__global__ __launch_bounds__(256) void ln_kernel(
    const float* __restrict__ x, const float* __restrict__ gam,
    const float* __restrict__ bet, float* __restrict__ y)
{
    int row = blockIdx.x;
    int t   = threadIdx.x;
    const float* xr = x + (long)row * H_;
    float a = xr[t];
    float b = xr[t + 256];
    float s = a + b;
    float q = a * a + b * b;
    #pragma unroll
    for (int off = 16; off > 0; off >>= 1) {
        s += __shfl_xor_sync(0xffffffffu, s, off);
        q += __shfl_xor_sync(0xffffffffu, q, off);
    }
    __shared__ float ss[8], qq[8];
    int w = t >> 5, lane = t & 31;
    if (lane == 0) { ss[w] = s; qq[w] = q; }
    __syncthreads();
    float S = 0.f, Q = 0.f;
    #pragma unroll
    for (int i = 0; i < 8; i++) { S += ss[i]; Q += qq[i]; }
    float mean = S * (1.f / H_);
    float var  = Q * (1.f / H_) - mean * mean;
    float inv  = rsqrtf(var + 1e-5f);
    float* yr = y + (long)row * H_;
    yr[t]       = to_tf32((a - mean) * inv * gam[t]       + bet[t]);
    yr[t + 256] = to_tf32((b - mean) * inv * gam[t + 256] + bet[t + 256]);
}

// ---------------- tf32 GEMM, cp.async 3-stage, 2 CTAs/SM ----------------
// C = A[M,K] @ W[K,N]. 128x128 tile, BK=16, 256 thr (2x4 warps, 64x32 warp tile).
// MODE 0: fused QKV scatter (Cout=q, out2=k, out3=v; N=1536, bias[1536])
// MODE 1: residual+bias   MODE 2: exact GELU (tf32 out)
#define ASTRIDE 2560   // 128*20 floats per stage
#define BSTRIDE 2176   // 16*136 floats per stage
template<int MODE>
__global__ __launch_bounds__(256, 2) void gemm_tc(
    const float* __restrict__ A, const float* __restrict__ Bm,
    const float* __restrict__ bias, const float* __restrict__ res,
    float* __restrict__ Cout, float* __restrict__ out2, float* __restrict__ out3,
    int Nd, int Kd)
{
    extern __shared__ float smp[];
    float* As = smp;                  // 3 stages of [128][20]
    float* Bs = smp + 3 * ASTRIDE;    // 3 stages of [16][136]

    const int tid = threadIdx.x;
    const int w   = tid >> 5;
    const int l   = tid & 31;
    const int wm  = w >> 2;
    const int wn  = w & 3;
    const int g   = l >> 2;
    const int tig = l & 3;

    const int aRow = tid >> 2;            // 0..63 (+64)
    const int aCol = (tid & 3) << 2;      // 0,4,8,12
    const int bRow = tid >> 5;            // 0..7 (+8)
    const int bCol = (tid & 31) << 2;     // 0..124

    const int bx = blockIdx.x, by = blockIdx.y;
    const float* Ab = A  + (long)(by * 128) * Kd;
    const float* Bb = Bm + bx * 128;

    const uint32_t sA = (uint32_t)__cvta_generic_to_shared(As);
    const uint32_t sB = (uint32_t)__cvta_generic_to_shared(Bs);

    float acc[4][4][4];
    #pragma unroll
    for (int i = 0; i < 4; i++)
        #pragma unroll
        for (int j = 0; j < 4; j++)
            #pragma unroll
            for (int r = 0; r < 4; r++) acc[i][j][r] = 0.f;

    const int nK = Kd >> 4;

    // issue loads for k-tile kt into stage st
    auto issue = [&](int kt, int st) {
        const int k0 = kt * 16;
        uint32_t a0 = sA + (st * ASTRIDE + aRow * 20 + aCol) * 4;
        uint32_t a1 = sA + (st * ASTRIDE + (aRow + 64) * 20 + aCol) * 4;
        cp_async16(a0, Ab + (long)aRow        * Kd + k0 + aCol);
        cp_async16(a1, Ab + (long)(aRow + 64) * Kd + k0 + aCol);
        uint32_t b0 = sB + (st * BSTRIDE + bRow * 136 + bCol) * 4;
        uint32_t b1 = sB + (st * BSTRIDE + (bRow + 8) * 136 + bCol) * 4;
        cp_async16(b0, Bb + (long)(k0 + bRow)     * Nd + bCol);
        cp_async16(b1, Bb + (long)(k0 + bRow + 8) * Nd + bCol);
    };

    issue(0, 0); cp_commit();
    issue(1, 1); cp_commit();

    int st = 0;
    for (int kt = 0; kt < nK; kt++) {
        cp_wait<1>();
        __syncthreads();

        const float* Asb = As + st * ASTRIDE;
        const float* Bsb = Bs + st * BSTRIDE;
        #pragma unroll
        for (int k0 = 0; k0 < 16; k0 += 8) {
            uint32_t af[4][4], bf[4][2];
            #pragma unroll
            for (int mt = 0; mt < 4; mt++) {
                int row = wm * 64 + mt * 16 + g;
                af[mt][0] = __float_as_uint(Asb[ row      * 20 + k0 + tig    ]);
                af[mt][1] = __float_as_uint(Asb[(row + 8) * 20 + k0 + tig    ]);
                af[mt][2] = __float_as_uint(Asb[ row      * 20 + k0 + tig + 4]);
                af[mt][3] = __float_as_uint(Asb[(row + 8) * 20 + k0 + tig + 4]);
            }
            #pragma unroll
            for (int nt = 0; nt < 4; nt++) {
                int col = wn * 32 + nt * 8 + g;
                bf[nt][0] = __float_as_uint(Bsb[(k0 + tig)     * 136 + col]);
                bf[nt][1] = __float_as_uint(Bsb[(k0 + tig + 4) * 136 + col]);
            }
            #pragma unroll
            for (int mt = 0; mt < 4; mt++)
                #pragma unroll
                for (int nt = 0; nt < 4; nt++)
                    mma_tf32(acc[mt][nt], af[mt], bf[nt][0], bf[nt][1]);
        }

        if (kt + 2 < nK) {
            int nst = st + 2; if (nst >= 3) nst -= 3;
            issue(kt + 2, nst);
        }
        cp_commit();
        st = st + 1 == 3 ? 0 : st + 1;
    }

    // ---- epilogue ----
    float* Cx = Cout;
    int nbase = bx * 128;
    if (MODE == 0) {
        int proj = bx >> 2;                 // 512 cols per projection, 4 tiles each
        Cx = proj == 0 ? Cout : (proj == 1 ? out2 : out3);
    }
    #pragma unroll
    for (int mt = 0; mt < 4; mt++) {
        #pragma unroll
        for (int half = 0; half < 2; half++) {
            int mr = by * 128 + wm * 64 + mt * 16 + g + half * 8;
            #pragma unroll
            for (int nt = 0; nt < 4; nt++) {
                int nc = nbase + wn * 32 + nt * 8 + 2 * tig;
                float v0 = acc[mt][nt][half * 2 + 0] + bias[nc];
                float v1 = acc[mt][nt][half * 2 + 1] + bias[nc + 1];
                if (MODE == 0) {
                    int b = mr >> 10, s = mr & 1023;
                    int h = (nc & 511) >> 6, d = nc & 63;
                    long idx = ((long)((b * NH_ + h) << 10) + s) * DH_ + d;
                    *(float2*)&Cx[idx] = make_float2(v0, v1);
                } else if (MODE == 1) {
                    long idx = (long)mr * Nd + nc;
                    float2 rv = *(const float2*)&res[idx];
                    *(float2*)&Cx[idx] = make_float2(rv.x + v0, rv.y + v1);
                } else {
                    long idx = (long)mr * Nd + nc;
                    float gelu0 = 0.5f * v0 * (1.f + erff(v0 * 0.70710678118f));
                    float gelu1 = 0.5f * v1 * (1.f + erff(v1 * 0.70710678118f));
                    *(float2*)&Cx[idx] = make_float2(to_tf32(gelu0), to_tf32(gelu1));
                }
            }
        }
    }
}

// ---------------- Tensor-core flash attention (unchanged from round 3) ----------------
__global__ __launch_bounds__(128) void attn_tc(
    const float* __restrict__ q, const float* __restrict__ k,
    const float* __restrict__ v, const float* __restrict__ bias,
    const int* __restrict__ mask, float* __restrict__ att)
{
    extern __shared__ float sm[];
    float* Qs = sm;                     // [64][68], later reused as Ps
    float* Ks = sm + 64 * 68;           // [64][65]  indexed [d][key]
    float* Vs = Ks + 64 * 65;           // [64][66]  indexed [key][d]

    const int h = blockIdx.x, qt = blockIdx.y, b = blockIdx.z;
    const int tid = threadIdx.x;
    const int w = tid >> 5, l = tid & 31;
    const int g = l >> 2, tig = l & 3;

    const long headoff = (long)((b * NH_ + h) * S_) * DH_;
    const float* qg = q + headoff + (long)qt * 64 * DH_;
    const float* kg = k + headoff;
    const float* vg = v + headoff;

    #pragma unroll
    for (int j = 0; j < 16; j++) {
        int lin = tid + j * 128;
        int r = lin >> 5, c2 = (lin & 31) * 2;
        float2 qv = *(const float2*)(qg + r * 64 + c2);
        Qs[r * 68 + c2]     = to_tf32(qv.x * 0.125f);
        Qs[r * 68 + c2 + 1] = to_tf32(qv.y * 0.125f);
    }
    __syncthreads();

    const int qrow = w * 16 + g;
    uint32_t qf[8][4];
    #pragma unroll
    for (int kk = 0; kk < 8; kk++) {
        qf[kk][0] = __float_as_uint(Qs[ qrow      * 68 + kk * 8 + tig    ]);
        qf[kk][1] = __float_as_uint(Qs[(qrow + 8) * 68 + kk * 8 + tig    ]);
        qf[kk][2] = __float_as_uint(Qs[ qrow      * 68 + kk * 8 + tig + 4]);
        qf[kk][3] = __float_as_uint(Qs[(qrow + 8) * 68 + kk * 8 + tig + 4]);
    }
    __syncthreads();

    float of[8][4];
    #pragma unroll
    for (int nt = 0; nt < 8; nt++)
        #pragma unroll
        for (int r = 0; r < 4; r++) of[nt][r] = 0.f;
    float m0 = -3.0e38f, m1 = -3.0e38f, l0 = 0.f, l1 = 0.f;

    const long srow0 = (long)b * S_ + qt * 64 + w * 16 + g;
    const float* brow0 = bias + srow0 * S_;
    const float* brow1 = brow0 + 8L * S_;
    const int*   mrow0 = mask + srow0 * S_;
    const int*   mrow1 = mrow0 + 8L * S_;

    float* Ps = Qs;

    for (int kt = 0; kt < S_ / 64; kt++) {
        #pragma unroll
        for (int j = 0; j < 16; j++) {
            int lin = tid + j * 128;
            int r = lin >> 5, c2 = (lin & 31) * 2;
            float2 kv = *(const float2*)(kg + (long)(kt * 64 + r) * 64 + c2);
            Ks[(c2    ) * 65 + r] = to_tf32(kv.x);
            Ks[(c2 + 1) * 65 + r] = to_tf32(kv.y);
            float2 vv = *(const float2*)(vg + (long)(kt * 64 + r) * 64 + c2);
            *(float2*)&Vs[r * 66 + c2] = make_float2(to_tf32(vv.x), to_tf32(vv.y));
        }
        __syncthreads();

        float sacc[8][4];
        #pragma unroll
        for (int nt = 0; nt < 8; nt++)
            #pragma unroll
            for (int r = 0; r < 4; r++) sacc[nt][r] = 0.f;
        #pragma unroll
        for (int kk = 0; kk < 8; kk++) {
            #pragma unroll
            for (int nt = 0; nt < 8; nt++) {
                uint32_t b0 = __float_as_uint(Ks[(kk * 8 + tig    ) * 65 + nt * 8 + g]);
                uint32_t b1 = __float_as_uint(Ks[(kk * 8 + tig + 4) * 65 + nt * 8 + g]);
                mma_tf32(sacc[nt], qf[kk], b0, b1);
            }
        }

        float tmax0 = -3.0e38f, tmax1 = -3.0e38f;
        #pragma unroll
        for (int nt = 0; nt < 8; nt++) {
            int kc = kt * 64 + nt * 8 + 2 * tig;
            float2 bv0 = *(const float2*)(brow0 + kc);
            float2 bv1 = *(const float2*)(brow1 + kc);
            int2   mv0 = *(const int2*)  (mrow0 + kc);
            int2   mv1 = *(const int2*)  (mrow1 + kc);
            sacc[nt][0] = mv0.x ? sacc[nt][0] + bv0.x : -1e9f;
            sacc[nt][1] = mv0.y ? sacc[nt][1] + bv0.y : -1e9f;
            sacc[nt][2] = mv1.x ? sacc[nt][2] + bv1.x : -1e9f;
            sacc[nt][3] = mv1.y ? sacc[nt][3] + bv1.y : -1e9f;
            tmax0 = fmaxf(tmax0, fmaxf(sacc[nt][0], sacc[nt][1]));
            tmax1 = fmaxf(tmax1, fmaxf(sacc[nt][2], sacc[nt][3]));
        }
        tmax0 = fmaxf(tmax0, __shfl_xor_sync(0xffffffffu, tmax0, 1));
        tmax0 = fmaxf(tmax0, __shfl_xor_sync(0xffffffffu, tmax0, 2));
        tmax1 = fmaxf(tmax1, __shfl_xor_sync(0xffffffffu, tmax1, 1));
        tmax1 = fmaxf(tmax1, __shfl_xor_sync(0xffffffffu, tmax1, 2));
        float mn0 = fmaxf(m0, tmax0), mn1 = fmaxf(m1, tmax1);
        float c0 = __expf(m0 - mn0), c1 = __expf(m1 - mn1);
        l0 *= c0; l1 *= c1;
        m0 = mn0; m1 = mn1;
        #pragma unroll
        for (int nt = 0; nt < 8; nt++) {
            of[nt][0] *= c0; of[nt][1] *= c0;
            of[nt][2] *= c1; of[nt][3] *= c1;
            float p0 = __expf(sacc[nt][0] - m0);
            float p1 = __expf(sacc[nt][1] - m0);
            float p2 = __expf(sacc[nt][2] - m1);
            float p3 = __expf(sacc[nt][3] - m1);
            l0 += p0 + p1; l1 += p2 + p3;
            *(float2*)&Ps[ qrow      * 68 + nt * 8 + 2 * tig] =
                make_float2(to_tf32(p0), to_tf32(p1));
            *(float2*)&Ps[(qrow + 8) * 68 + nt * 8 + 2 * tig] =
                make_float2(to_tf32(p2), to_tf32(p3));
        }
        __syncwarp();

        #pragma unroll
        for (int kk = 0; kk < 8; kk++) {
            uint32_t pf[4];
            pf[0] = __float_as_uint(Ps[ qrow      * 68 + kk * 8 + tig    ]);
            pf[1] = __float_as_uint(Ps[(qrow + 8) * 68 + kk * 8 + tig    ]);
            pf[2] = __float_as_uint(Ps[ qrow      * 68 + kk * 8 + tig + 4]);
            pf[3] = __float_as_uint(Ps[(qrow + 8) * 68 + kk * 8 + tig + 4]);
            #pragma unroll
            for (int nt = 0; nt < 8; nt++) {
                uint32_t b0 = __float_as_uint(Vs[(kk * 8 + tig    ) * 66 + nt * 8 + g]);
                uint32_t b1 = __float_as_uint(Vs[(kk * 8 + tig + 4) * 66 + nt * 8 + g]);
                mma_tf32(of[nt], pf, b0, b1);
            }
        }
        __syncthreads();
    }

    l0 += __shfl_xor_sync(0xffffffffu, l0, 1);
    l0 += __shfl_xor_sync(0xffffffffu, l0, 2);
    l1 += __shfl_xor_sync(0xffffffffu, l1, 1);
    l1 += __shfl_xor_sync(0xffffffffu, l1, 2);
    float inv0 = 1.f / l0, inv1 = 1.f / l1;

    const long orow0 = (long)b * S_ + qt * 64 + w * 16 + g;
    #pragma unroll
    for (int nt = 0; nt < 8; nt++) {
        int col = h * 64 + nt * 8 + 2 * tig;
        *(float2*)&att[ orow0      * H_ + col] =
            make_float2(to_tf32(of[nt][0] * inv0), to_tf32(of[nt][1] * inv0));
        *(float2*)&att[(orow0 + 8) * H_ + col] =
            make_float2(to_tf32(of[nt][2] * inv1), to_tf32(of[nt][3] * inv1));
    }
}

// ---------------- launch ----------------
extern "C" void kernel_launch(void* const* d_in, const int* in_sizes, int n_in,
                              void* d_out, int out_size)
{
    const float* x     = (const float*)d_in[0];
    const float* abias = (const float*)d_in[1];
    const int*   gmask = (const int*)  d_in[2];
    const float* ln1g  = (const float*)d_in[3];
    const float* ln1b  = (const float*)d_in[4];
    const float* Wq    = (const float*)d_in[5];
    const float* bq    = (const float*)d_in[6];
    const float* Wk    = (const float*)d_in[7];
    const float* bk    = (const float*)d_in[8];
    const float* Wv    = (const float*)d_in[9];
    const float* bv    = (const float*)d_in[10];
    const float* Wo    = (const float*)d_in[11];
    const float* bo    = (const float*)d_in[12];
    const float* ln2g  = (const float*)d_in[13];
    const float* ln2b  = (const float*)d_in[14];
    const float* W1    = (const float*)d_in[15];
    const float* b1    = (const float*)d_in[16];
    const float* W2    = (const float*)d_in[17];
    const float* b2    = (const float*)d_in[18];
    float* out = (float*)d_out;

    float *yb, *qb, *kb, *vb, *ab, *x1b, *h1b;
    float *wqkv, *bqkv, *wo, *w1, *w2;
    cudaGetSymbolAddress((void**)&yb,   g_y);
    cudaGetSymbolAddress((void**)&qb,   g_q);
    cudaGetSymbolAddress((void**)&kb,   g_k);
    cudaGetSymbolAddress((void**)&vb,   g_v);
    cudaGetSymbolAddress((void**)&ab,   g_att);
    cudaGetSymbolAddress((void**)&x1b,  g_x1);
    cudaGetSymbolAddress((void**)&h1b,  g_h1);
    cudaGetSymbolAddress((void**)&wqkv, g_wqkv);
    cudaGetSymbolAddress((void**)&bqkv, g_bqkv);
    cudaGetSymbolAddress((void**)&wo,   g_wo);
    cudaGetSymbolAddress((void**)&w1,   g_w1);
    cudaGetSymbolAddress((void**)&w2,   g_w2);

    const int GEMM_SMEM = 3 * (ASTRIDE + BSTRIDE) * 4;          // 56832 B
    const int ATTN_SMEM = (64 * 68 + 64 * 65 + 64 * 66) * 4;    // 50944 B
    static int attr_set = 0;
    if (!attr_set) {
        cudaFuncSetAttribute(gemm_tc<0>, cudaFuncAttributeMaxDynamicSharedMemorySize, GEMM_SMEM);
        cudaFuncSetAttribute(gemm_tc<1>, cudaFuncAttributeMaxDynamicSharedMemorySize, GEMM_SMEM);
        cudaFuncSetAttribute(gemm_tc<2>, cudaFuncAttributeMaxDynamicSharedMemorySize, GEMM_SMEM);
        cudaFuncSetAttribute(attn_tc,    cudaFuncAttributeMaxDynamicSharedMemorySize, ATTN_SMEM);
        attr_set = 1;
    }

    cvt_qkv_kernel<<<(H_*H_ + 255)/256, 256>>>(Wq, Wk, Wv, wqkv);
    cat_bias_kernel<<<2, 256>>>(bq, bk, bv, bqkv);
    cvt_kernel<<<(H_*H_   + 255)/256, 256>>>(Wo, wo, H_*H_);
    cvt_kernel<<<(H_*FFN_ + 255)/256, 256>>>(W1, w1, H_*FFN_);
    cvt_kernel<<<(FFN_*H_ + 255)/256, 256>>>(W2, w2, FFN_*H_);

    dim3 gQKV(12, 64);
    dim3 gH(4, 64);
    dim3 gF(16, 64);

    ln_kernel<<<M_, 256>>>(x, ln1g, ln1b, yb);
    gemm_tc<0><<<gQKV, 256, GEMM_SMEM>>>(yb, wqkv, bqkv, nullptr, qb, kb, vb, 1536, H_);
    attn_tc<<<dim3(NH_, S_ / 64, B_), 128, ATTN_SMEM>>>(qb, kb, vb, abias, gmask, ab);
    gemm_tc<1><<<gH, 256, GEMM_SMEM>>>(ab, wo, bo, x, x1b, nullptr, nullptr, H_, H_);
    ln_kernel<<<M_, 256>>>(x1b, ln2g, ln2b, yb);
    gemm_tc<2><<<gF, 256, GEMM_SMEM>>>(yb, w1, b1, nullptr, h1b, nullptr, nullptr, FFN_, H_);
    gemm_tc<1><<<gH, 256, GEMM_SMEM>>>(h1b, w2, b2, x1b, out, nullptr, nullptr, H_, FFN_);
}

// round 6
// speedup vs baseline: 3.1439x; 1.2019x over previous
#include <cuda_runtime.h>
#include <cuda_bf16.h>
#include <math.h>
#include <stdint.h>

#define B_   8
#define S_   1024
#define H_   512
#define NH_  8
#define DH_  64
#define FFN_ 2048
#define M_   (B_*S_)

// ---------------- scratch (device globals; no allocation allowed) ----------------
__device__ __align__(16) __nv_bfloat16 g_y  [M_*H_];
__device__ __align__(16) float         g_q  [M_*H_];
__device__ __align__(16) float         g_k  [M_*H_];
__device__ __align__(16) float         g_v  [M_*H_];
__device__ __align__(16) __nv_bfloat16 g_att[M_*H_];
__device__ __align__(16) float         g_x1 [M_*H_];
__device__ __align__(16) __nv_bfloat16 g_h1 [M_*FFN_];
// bf16 weights
__device__ __align__(16) __nv_bfloat16 g_wqkv[H_*3*H_];
__device__ float g_bqkv[3*H_];
__device__ __align__(16) __nv_bfloat16 g_wo [H_*H_];
__device__ __align__(16) __nv_bfloat16 g_w1 [H_*FFN_];
__device__ __align__(16) __nv_bfloat16 g_w2 [FFN_*H_];

__device__ __forceinline__ float to_tf32(float x) {
    float r;
    asm("cvt.rna.tf32.f32 %0, %1;" : "=f"(r) : "f"(x));
    return r;
}

__device__ __forceinline__ void mma_tf32(float* c, const uint32_t* a,
                                         uint32_t b0, uint32_t b1) {
    asm("mma.sync.aligned.m16n8k8.row.col.f32.tf32.tf32.f32 "
        "{%0,%1,%2,%3}, {%4,%5,%6,%7}, {%8,%9}, {%0,%1,%2,%3};"
        : "+f"(c[0]), "+f"(c[1]), "+f"(c[2]), "+f"(c[3])
        : "r"(a[0]), "r"(a[1]), "r"(a[2]), "r"(a[3]), "r"(b0), "r"(b1));
}

__device__ __forceinline__ void mma_bf16(float* c, const uint32_t* a,
                                         uint32_t b0, uint32_t b1) {
    asm("mma.sync.aligned.m16n8k16.row.col.f32.bf16.bf16.f32 "
        "{%0,%1,%2,%3}, {%4,%5,%6,%7}, {%8,%9}, {%0,%1,%2,%3};"
        : "+f"(c[0]), "+f"(c[1]), "+f"(c[2]), "+f"(c[3])
        : "r"(a[0]), "r"(a[1]), "r"(a[2]), "r"(a[3]), "r"(b0), "r"(b1));
}

__device__ __forceinline__ void ldsm_x4(uint32_t& r0, uint32_t& r1,
                                        uint32_t& r2, uint32_t& r3, uint32_t addr) {
    asm volatile("ldmatrix.sync.aligned.m8n8.x4.shared.b16 {%0,%1,%2,%3}, [%4];"
                 : "=r"(r0), "=r"(r1), "=r"(r2), "=r"(r3) : "r"(addr));
}
__device__ __forceinline__ void ldsm_x4t(uint32_t& r0, uint32_t& r1,
                                         uint32_t& r2, uint32_t& r3, uint32_t addr) {
    asm volatile("ldmatrix.sync.aligned.m8n8.x4.trans.shared.b16 {%0,%1,%2,%3}, [%4];"
                 : "=r"(r0), "=r"(r1), "=r"(r2), "=r"(r3) : "r"(addr));
}

__device__ __forceinline__ void cp_async16(uint32_t smem_dst, const void* gsrc) {
    asm volatile("cp.async.cg.shared.global [%0], [%1], 16;"
                 :: "r"(smem_dst), "l"(gsrc));
}
__device__ __forceinline__ void cp_commit() {
    asm volatile("cp.async.commit_group;");
}
template<int N>
__device__ __forceinline__ void cp_wait() {
    asm volatile("cp.async.wait_group %0;" :: "n"(N));
}

// ---------------- weight prep (fp32 -> bf16) ----------------
__global__ __launch_bounds__(256) void cvt_kernel(const float* __restrict__ in,
                                                  __nv_bfloat16* __restrict__ out, int n)
{
    int i = blockIdx.x * 256 + threadIdx.x;
    if (i < n) out[i] = __float2bfloat16_rn(in[i]);
}

// pack Wq|Wk|Wv side by side into [K=512][N=1536], bf16
__global__ __launch_bounds__(256) void cvt_qkv_kernel(
    const float* __restrict__ wq, const float* __restrict__ wk,
    const float* __restrict__ wv, __nv_bfloat16* __restrict__ out)
{
    int i = blockIdx.x * 256 + threadIdx.x;
    if (i < H_ * H_) {
        int k = i >> 9, n = i & 511;
        out[k * 1536 + n]        = __float2bfloat16_rn(wq[i]);
        out[k * 1536 + 512 + n]  = __float2bfloat16_rn(wk[i]);
        out[k * 1536 + 1024 + n] = __float2bfloat16_rn(wv[i]);
    }
}

__global__ __launch_bounds__(256) void cat_bias_kernel(
    const float* __restrict__ a, const float* __restrict__ b,
    const float* __restrict__ c, float* __restrict__ o)
{
    int i = blockIdx.x * 256 + threadIdx.x;
    if (i < 512) { o[i] = a[i]; o[i + 512] = b[i]; o[i + 1024] = c[i]; }
}

// ---------------- LayerNorm (bf16 out) ----------------
__global__ __launch_bounds__(256) void ln_kernel(
    const float* __restrict__ x, const float* __restrict__ gam,
    const float* __restrict__ bet, __nv_bfloat16* __restrict__ y)
{
    int row = blockIdx.x;
    int t   = threadIdx.x;
    const float* xr = x + (long)row * H_;
    float a = xr[t];
    float b = xr[t + 256];
    float s = a + b;
    float q = a * a + b * b;
    #pragma unroll
    for (int off = 16; off > 0; off >>= 1) {
        s += __shfl_xor_sync(0xffffffffu, s, off);
        q += __shfl_xor_sync(0xffffffffu, q, off);
    }
    __shared__ float ss[8], qq[8];
    int w = t >> 5, lane = t & 31;
    if (lane == 0) { ss[w] = s; qq[w] = q; }
    __syncthreads();
    float S = 0.f, Q = 0.f;
    #pragma unroll
    for (int i = 0; i < 8; i++) { S += ss[i]; Q += qq[i]; }
    float mean = S * (1.f / H_);
    float var  = Q * (1.f / H_) - mean * mean;
    float inv  = rsqrtf(var + 1e-5f);
    __nv_bfloat16* yr = y + (long)row * H_;
    yr[t]       = __float2bfloat16_rn((a - mean) * inv * gam[t]       + bet[t]);
    yr[t + 256] = __float2bfloat16_rn((b - mean) * inv * gam[t + 256] + bet[t + 256]);
}

// ---------------- bf16 GEMM, ldmatrix + m16n8k16, cp.async 3-stage ----------------
// C = A[M,K] @ W[K,N], A/W bf16. 128x128 tile, BK=32, 256 thr (2x4 warps, 64x32 warp).
// MODE 0: fused QKV scatter (float q/k/v)  MODE 1: residual+bias (float)
// MODE 2: exact GELU -> bf16
#define ASTAGE 5120    // 128*40 bf16 per stage (row stride 40 = 80B, conflict-free)
#define BSTAGE 4352    // 32*136 bf16 per stage (row stride 136 = 272B, conflict-free)
template<int MODE>
__global__ __launch_bounds__(256, 2) void gemm_tc(
    const __nv_bfloat16* __restrict__ A, const __nv_bfloat16* __restrict__ Bm,
    const float* __restrict__ bias, const float* __restrict__ res,
    void* __restrict__ CoutV, float* __restrict__ out2, float* __restrict__ out3,
    int Nd, int Kd)
{
    extern __shared__ __align__(16) __nv_bfloat16 smp[];
    __nv_bfloat16* As = smp;                 // 3 stages
    __nv_bfloat16* Bs = smp + 3 * ASTAGE;

    const int tid = threadIdx.x;
    const int w   = tid >> 5;
    const int l   = tid & 31;
    const int wm  = w >> 2;               // 0..1
    const int wn  = w & 3;                // 0..3
    const int g   = l >> 2;
    const int tig = l & 3;

    const int bx = blockIdx.x, by = blockIdx.y;
    const __nv_bfloat16* Ab = A  + (long)(by * 128) * Kd;
    const __nv_bfloat16* Bb = Bm + bx * 128;

    const uint32_t sA = (uint32_t)__cvta_generic_to_shared(As);
    const uint32_t sB = (uint32_t)__cvta_generic_to_shared(Bs);

    // ldmatrix per-lane byte offsets (within a stage)
    const uint32_t aOff = ((uint32_t)(wm * 64 + (l & 15)) * 40) * 2 + (l >> 4) * 16;
    const uint32_t bOff = ((uint32_t)((l & 15)) * 136 + wn * 32) * 2 + (l >> 4) * 16;

    // cp.async assignments
    const int aRow = tid >> 1;            // 0..127
    const int aK   = (tid & 1) * 16;      // bf16 col offset within BK=32
    const int bRow = tid >> 3;            // 0..31
    const int bCol = (tid & 7) * 16;      // bf16 col offset within 128

    float acc[4][4][4];
    #pragma unroll
    for (int i = 0; i < 4; i++)
        #pragma unroll
        for (int j = 0; j < 4; j++)
            #pragma unroll
            for (int r = 0; r < 4; r++) acc[i][j][r] = 0.f;

    const int nK = Kd >> 5;               // BK=32

    auto issue = [&](int kt, int st) {
        const int k0 = kt * 32;
        uint32_t ad = sA + (st * ASTAGE + aRow * 40 + aK) * 2;
        const __nv_bfloat16* asrc = Ab + (long)aRow * Kd + k0 + aK;
        cp_async16(ad,      asrc);
        cp_async16(ad + 16, asrc + 8);
        uint32_t bd = sB + (st * BSTAGE + bRow * 136 + bCol) * 2;
        const __nv_bfloat16* bsrc = Bb + (long)(k0 + bRow) * Nd + bCol;
        cp_async16(bd,      bsrc);
        cp_async16(bd + 16, bsrc + 8);
    };

    issue(0, 0); cp_commit();
    issue(1, 1); cp_commit();

    int st = 0;
    for (int kt = 0; kt < nK; kt++) {
        cp_wait<1>();
        __syncthreads();

        const uint32_t aB = sA + st * ASTAGE * 2 + aOff;
        const uint32_t bB = sB + st * BSTAGE * 2 + bOff;

        #pragma unroll
        for (int kc = 0; kc < 2; kc++) {
            uint32_t af[4][4], bf[2][4];
            #pragma unroll
            for (int mt = 0; mt < 4; mt++)
                ldsm_x4(af[mt][0], af[mt][1], af[mt][2], af[mt][3],
                        aB + mt * 1280 + kc * 32);
            #pragma unroll
            for (int np = 0; np < 2; np++)
                ldsm_x4t(bf[np][0], bf[np][1], bf[np][2], bf[np][3],
                         bB + kc * 4352 + np * 32);
            #pragma unroll
            for (int mt = 0; mt < 4; mt++)
                #pragma unroll
                for (int n8 = 0; n8 < 4; n8++) {
                    uint32_t b0 = bf[n8 >> 1][(n8 & 1) * 2];
                    uint32_t b1 = bf[n8 >> 1][(n8 & 1) * 2 + 1];
                    mma_bf16(acc[mt][n8], af[mt], b0, b1);
                }
        }

        if (kt + 2 < nK) {
            int nst = st + 2; if (nst >= 3) nst -= 3;
            issue(kt + 2, nst);
        }
        cp_commit();
        st = st + 1 == 3 ? 0 : st + 1;
    }

    // ---- epilogue ----
    float* Cf = (float*)CoutV;
    __nv_bfloat16* Ch = (__nv_bfloat16*)CoutV;
    int nbase = bx * 128;
    if (MODE == 0) {
        int proj = bx >> 2;
        Cf = proj == 0 ? (float*)CoutV : (proj == 1 ? out2 : out3);
    }
    #pragma unroll
    for (int mt = 0; mt < 4; mt++) {
        #pragma unroll
        for (int half = 0; half < 2; half++) {
            int mr = by * 128 + wm * 64 + mt * 16 + g + half * 8;
            #pragma unroll
            for (int nt = 0; nt < 4; nt++) {
                int nc = nbase + wn * 32 + nt * 8 + 2 * tig;
                float v0 = acc[mt][nt][half * 2 + 0] + bias[nc];
                float v1 = acc[mt][nt][half * 2 + 1] + bias[nc + 1];
                if (MODE == 0) {
                    int b = mr >> 10, s = mr & 1023;
                    int h = (nc & 511) >> 6, d = nc & 63;
                    long idx = ((long)((b * NH_ + h) << 10) + s) * DH_ + d;
                    *(float2*)&Cf[idx] = make_float2(v0, v1);
                } else if (MODE == 1) {
                    long idx = (long)mr * Nd + nc;
                    float2 rv = *(const float2*)&res[idx];
                    *(float2*)&Cf[idx] = make_float2(rv.x + v0, rv.y + v1);
                } else {
                    long idx = (long)mr * Nd + nc;
                    float g0 = 0.5f * v0 * (1.f + erff(v0 * 0.70710678118f));
                    float g1 = 0.5f * v1 * (1.f + erff(v1 * 0.70710678118f));
                    *(__nv_bfloat162*)&Ch[idx] = __floats2bfloat162_rn(g0, g1);
                }
            }
        }
    }
}

// ---------------- Tensor-core flash attention (tf32, bf16 output) ----------------
__global__ __launch_bounds__(128) void attn_tc(
    const float* __restrict__ q, const float* __restrict__ k,
    const float* __restrict__ v, const float* __restrict__ bias,
    const int* __restrict__ mask, __nv_bfloat16* __restrict__ att)
{
    extern __shared__ float sm[];
    float* Qs = sm;                     // [64][68], later reused as Ps
    float* Ks = sm + 64 * 68;           // [64][65]  indexed [d][key]
    float* Vs = Ks + 64 * 65;           // [64][66]  indexed [key][d]

    const int h = blockIdx.x, qt = blockIdx.y, b = blockIdx.z;
    const int tid = threadIdx.x;
    const int w = tid >> 5, l = tid & 31;
    const int g = l >> 2, tig = l & 3;

    const long headoff = (long)((b * NH_ + h) * S_) * DH_;
    const float* qg = q + headoff + (long)qt * 64 * DH_;
    const float* kg = k + headoff;
    const float* vg = v + headoff;

    #pragma unroll
    for (int j = 0; j < 16; j++) {
        int lin = tid + j * 128;
        int r = lin >> 5, c2 = (lin & 31) * 2;
        float2 qv = *(const float2*)(qg + r * 64 + c2);
        Qs[r * 68 + c2]     = to_tf32(qv.x * 0.125f);
        Qs[r * 68 + c2 + 1] = to_tf32(qv.y * 0.125f);
    }
    __syncthreads();

    const int qrow = w * 16 + g;
    uint32_t qf[8][4];
    #pragma unroll
    for (int kk = 0; kk < 8; kk++) {
        qf[kk][0] = __float_as_uint(Qs[ qrow      * 68 + kk * 8 + tig    ]);
        qf[kk][1] = __float_as_uint(Qs[(qrow + 8) * 68 + kk * 8 + tig    ]);
        qf[kk][2] = __float_as_uint(Qs[ qrow      * 68 + kk * 8 + tig + 4]);
        qf[kk][3] = __float_as_uint(Qs[(qrow + 8) * 68 + kk * 8 + tig + 4]);
    }
    __syncthreads();

    float of[8][4];
    #pragma unroll
    for (int nt = 0; nt < 8; nt++)
        #pragma unroll
        for (int r = 0; r < 4; r++) of[nt][r] = 0.f;
    float m0 = -3.0e38f, m1 = -3.0e38f, l0 = 0.f, l1 = 0.f;

    const long srow0 = (long)b * S_ + qt * 64 + w * 16 + g;
    const float* brow0 = bias + srow0 * S_;
    const float* brow1 = brow0 + 8L * S_;
    const int*   mrow0 = mask + srow0 * S_;
    const int*   mrow1 = mrow0 + 8L * S_;

    float* Ps = Qs;

    for (int kt = 0; kt < S_ / 64; kt++) {
        #pragma unroll
        for (int j = 0; j < 16; j++) {
            int lin = tid + j * 128;
            int r = lin >> 5, c2 = (lin & 31) * 2;
            float2 kv = *(const float2*)(kg + (long)(kt * 64 + r) * 64 + c2);
            Ks[(c2    ) * 65 + r] = to_tf32(kv.x);
            Ks[(c2 + 1) * 65 + r] = to_tf32(kv.y);
            float2 vv = *(const float2*)(vg + (long)(kt * 64 + r) * 64 + c2);
            *(float2*)&Vs[r * 66 + c2] = make_float2(to_tf32(vv.x), to_tf32(vv.y));
        }
        __syncthreads();

        float sacc[8][4];
        #pragma unroll
        for (int nt = 0; nt < 8; nt++)
            #pragma unroll
            for (int r = 0; r < 4; r++) sacc[nt][r] = 0.f;
        #pragma unroll
        for (int kk = 0; kk < 8; kk++) {
            #pragma unroll
            for (int nt = 0; nt < 8; nt++) {
                uint32_t b0 = __float_as_uint(Ks[(kk * 8 + tig    ) * 65 + nt * 8 + g]);
                uint32_t b1 = __float_as_uint(Ks[(kk * 8 + tig + 4) * 65 + nt * 8 + g]);
                mma_tf32(sacc[nt], qf[kk], b0, b1);
            }
        }

        float tmax0 = -3.0e38f, tmax1 = -3.0e38f;
        #pragma unroll
        for (int nt = 0; nt < 8; nt++) {
            int kc = kt * 64 + nt * 8 + 2 * tig;
            float2 bv0 = *(const float2*)(brow0 + kc);
            float2 bv1 = *(const float2*)(brow1 + kc);
            int2   mv0 = *(const int2*)  (mrow0 + kc);
            int2   mv1 = *(const int2*)  (mrow1 + kc);
            sacc[nt][0] = mv0.x ? sacc[nt][0] + bv0.x : -1e9f;
            sacc[nt][1] = mv0.y ? sacc[nt][1] + bv0.y : -1e9f;
            sacc[nt][2] = mv1.x ? sacc[nt][2] + bv1.x : -1e9f;
            sacc[nt][3] = mv1.y ? sacc[nt][3] + bv1.y : -1e9f;
            tmax0 = fmaxf(tmax0, fmaxf(sacc[nt][0], sacc[nt][1]));
            tmax1 = fmaxf(tmax1, fmaxf(sacc[nt][2], sacc[nt][3]));
        }
        tmax0 = fmaxf(tmax0, __shfl_xor_sync(0xffffffffu, tmax0, 1));
        tmax0 = fmaxf(tmax0, __shfl_xor_sync(0xffffffffu, tmax0, 2));
        tmax1 = fmaxf(tmax1, __shfl_xor_sync(0xffffffffu, tmax1, 1));
        tmax1 = fmaxf(tmax1, __shfl_xor_sync(0xffffffffu, tmax1, 2));
        float mn0 = fmaxf(m0, tmax0), mn1 = fmaxf(m1, tmax1);
        float c0 = __expf(m0 - mn0), c1 = __expf(m1 - mn1);
        l0 *= c0; l1 *= c1;
        m0 = mn0; m1 = mn1;
        #pragma unroll
        for (int nt = 0; nt < 8; nt++) {
            of[nt][0] *= c0; of[nt][1] *= c0;
            of[nt][2] *= c1; of[nt][3] *= c1;
            float p0 = __expf(sacc[nt][0] - m0);
            float p1 = __expf(sacc[nt][1] - m0);
            float p2 = __expf(sacc[nt][2] - m1);
            float p3 = __expf(sacc[nt][3] - m1);
            l0 += p0 + p1; l1 += p2 + p3;
            *(float2*)&Ps[ qrow      * 68 + nt * 8 + 2 * tig] =
                make_float2(to_tf32(p0), to_tf32(p1));
            *(float2*)&Ps[(qrow + 8) * 68 + nt * 8 + 2 * tig] =
                make_float2(to_tf32(p2), to_tf32(p3));
        }
        __syncwarp();

        #pragma unroll
        for (int kk = 0; kk < 8; kk++) {
            uint32_t pf[4];
            pf[0] = __float_as_uint(Ps[ qrow      * 68 + kk * 8 + tig    ]);
            pf[1] = __float_as_uint(Ps[(qrow + 8) * 68 + kk * 8 + tig    ]);
            pf[2] = __float_as_uint(Ps[ qrow      * 68 + kk * 8 + tig + 4]);
            pf[3] = __float_as_uint(Ps[(qrow + 8) * 68 + kk * 8 + tig + 4]);
            #pragma unroll
            for (int nt = 0; nt < 8; nt++) {
                uint32_t b0 = __float_as_uint(Vs[(kk * 8 + tig    ) * 66 + nt * 8 + g]);
                uint32_t b1 = __float_as_uint(Vs[(kk * 8 + tig + 4) * 66 + nt * 8 + g]);
                mma_tf32(of[nt], pf, b0, b1);
            }
        }
        __syncthreads();
    }

    l0 += __shfl_xor_sync(0xffffffffu, l0, 1);
    l0 += __shfl_xor_sync(0xffffffffu, l0, 2);
    l1 += __shfl_xor_sync(0xffffffffu, l1, 1);
    l1 += __shfl_xor_sync(0xffffffffu, l1, 2);
    float inv0 = 1.f / l0, inv1 = 1.f / l1;

    const long orow0 = (long)b * S_ + qt * 64 + w * 16 + g;
    #pragma unroll
    for (int nt = 0; nt < 8; nt++) {
        int col = h * 64 + nt * 8 + 2 * tig;
        *(__nv_bfloat162*)&att[ orow0      * H_ + col] =
            __floats2bfloat162_rn(of[nt][0] * inv0, of[nt][1] * inv0);
        *(__nv_bfloat162*)&att[(orow0 + 8) * H_ + col] =
            __floats2bfloat162_rn(of[nt][2] * inv1, of[nt][3] * inv1);
    }
}

// ---------------- launch ----------------
extern "C" void kernel_launch(void* const* d_in, const int* in_sizes, int n_in,
                              void* d_out, int out_size)
{
    const float* x     = (const float*)d_in[0];
    const float* abias = (const float*)d_in[1];
    const int*   gmask = (const int*)  d_in[2];
    const float* ln1g  = (const float*)d_in[3];
    const float* ln1b  = (const float*)d_in[4];
    const float* Wq    = (const float*)d_in[5];
    const float* bq    = (const float*)d_in[6];
    const float* Wk    = (const float*)d_in[7];
    const float* bk    = (const float*)d_in[8];
    const float* Wv    = (const float*)d_in[9];
    const float* bv    = (const float*)d_in[10];
    const float* Wo    = (const float*)d_in[11];
    const float* bo    = (const float*)d_in[12];
    const float* ln2g  = (const float*)d_in[13];
    const float* ln2b  = (const float*)d_in[14];
    const float* W1    = (const float*)d_in[15];
    const float* b1    = (const float*)d_in[16];
    const float* W2    = (const float*)d_in[17];
    const float* b2    = (const float*)d_in[18];
    float* out = (float*)d_out;

    __nv_bfloat16 *yb, *ab, *h1b, *wqkv, *wo, *w1, *w2;
    float *qb, *kb, *vb, *x1b, *bqkv;
    cudaGetSymbolAddress((void**)&yb,   g_y);
    cudaGetSymbolAddress((void**)&qb,   g_q);
    cudaGetSymbolAddress((void**)&kb,   g_k);
    cudaGetSymbolAddress((void**)&vb,   g_v);
    cudaGetSymbolAddress((void**)&ab,   g_att);
    cudaGetSymbolAddress((void**)&x1b,  g_x1);
    cudaGetSymbolAddress((void**)&h1b,  g_h1);
    cudaGetSymbolAddress((void**)&wqkv, g_wqkv);
    cudaGetSymbolAddress((void**)&bqkv, g_bqkv);
    cudaGetSymbolAddress((void**)&wo,   g_wo);
    cudaGetSymbolAddress((void**)&w1,   g_w1);
    cudaGetSymbolAddress((void**)&w2,   g_w2);

    const int GEMM_SMEM = 3 * (ASTAGE + BSTAGE) * 2;            // 56832 B
    const int ATTN_SMEM = (64 * 68 + 64 * 65 + 64 * 66) * 4;    // 50944 B
    static int attr_set = 0;
    if (!attr_set) {
        cudaFuncSetAttribute(gemm_tc<0>, cudaFuncAttributeMaxDynamicSharedMemorySize, GEMM_SMEM);
        cudaFuncSetAttribute(gemm_tc<1>, cudaFuncAttributeMaxDynamicSharedMemorySize, GEMM_SMEM);
        cudaFuncSetAttribute(gemm_tc<2>, cudaFuncAttributeMaxDynamicSharedMemorySize, GEMM_SMEM);
        cudaFuncSetAttribute(attn_tc,    cudaFuncAttributeMaxDynamicSharedMemorySize, ATTN_SMEM);
        attr_set = 1;
    }

    cvt_qkv_kernel<<<(H_*H_ + 255)/256, 256>>>(Wq, Wk, Wv, wqkv);
    cat_bias_kernel<<<2, 256>>>(bq, bk, bv, bqkv);
    cvt_kernel<<<(H_*H_   + 255)/256, 256>>>(Wo, wo, H_*H_);
    cvt_kernel<<<(H_*FFN_ + 255)/256, 256>>>(W1, w1, H_*FFN_);
    cvt_kernel<<<(FFN_*H_ + 255)/256, 256>>>(W2, w2, FFN_*H_);

    dim3 gQKV(12, 64);
    dim3 gH(4, 64);
    dim3 gF(16, 64);

    ln_kernel<<<M_, 256>>>(x, ln1g, ln1b, yb);
    gemm_tc<0><<<gQKV, 256, GEMM_SMEM>>>(yb, wqkv, bqkv, nullptr, (void*)qb, kb, vb, 1536, H_);
    attn_tc<<<dim3(NH_, S_ / 64, B_), 128, ATTN_SMEM>>>(qb, kb, vb, abias, gmask, ab);
    gemm_tc<1><<<gH, 256, GEMM_SMEM>>>(ab, wo, bo, x, (void*)x1b, nullptr, nullptr, H_, H_);
    ln_kernel<<<M_, 256>>>(x1b, ln2g, ln2b, yb);
    gemm_tc<2><<<gF, 256, GEMM_SMEM>>>(yb, w1, b1, nullptr, (void*)h1b, nullptr, nullptr, FFN_, H_);
    gemm_tc<1><<<gH, 256, GEMM_SMEM>>>(h1b, w2, b2, x1b, (void*)out, nullptr, nullptr, H_, FFN_);
}

// round 8
// speedup vs baseline: 3.8297x; 1.2181x over previous
#include <cuda_runtime.h>
#include <cuda_bf16.h>
#include <math.h>
#include <stdint.h>

#define B_   8
#define S_   1024
#define H_   512
#define NH_  8
#define DH_  64
#define FFN_ 2048
#define M_   (B_*S_)

// ---------------- scratch (device globals; no allocation allowed) ----------------
__device__ __align__(16) __nv_bfloat16 g_y  [M_*H_];
__device__ __align__(16) float         g_q  [M_*H_];
__device__ __align__(16) float         g_k  [M_*H_];
__device__ __align__(16) float         g_v  [M_*H_];
__device__ __align__(16) __nv_bfloat16 g_att[M_*H_];
__device__ __align__(16) float         g_x1 [M_*H_];
__device__ __align__(16) __nv_bfloat16 g_h1 [M_*FFN_];
__device__ __align__(16) float         g_beff[B_*S_*S_];   // fused mask+bias
// bf16 weights
__device__ __align__(16) __nv_bfloat16 g_wqkv[H_*3*H_];
__device__ float g_bqkv[3*H_];
__device__ __align__(16) __nv_bfloat16 g_wo [H_*H_];
__device__ __align__(16) __nv_bfloat16 g_w1 [H_*FFN_];
__device__ __align__(16) __nv_bfloat16 g_w2 [FFN_*H_];

__device__ __forceinline__ float to_tf32(float x) {
    float r;
    asm("cvt.rna.tf32.f32 %0, %1;" : "=f"(r) : "f"(x));
    return r;
}

__device__ __forceinline__ void mma_tf32(float* c, const uint32_t* a,
                                         uint32_t b0, uint32_t b1) {
    asm("mma.sync.aligned.m16n8k8.row.col.f32.tf32.tf32.f32 "
        "{%0,%1,%2,%3}, {%4,%5,%6,%7}, {%8,%9}, {%0,%1,%2,%3};"
        : "+f"(c[0]), "+f"(c[1]), "+f"(c[2]), "+f"(c[3])
        : "r"(a[0]), "r"(a[1]), "r"(a[2]), "r"(a[3]), "r"(b0), "r"(b1));
}

__device__ __forceinline__ void mma_bf16(float* c, const uint32_t* a,
                                         uint32_t b0, uint32_t b1) {
    asm("mma.sync.aligned.m16n8k16.row.col.f32.bf16.bf16.f32 "
        "{%0,%1,%2,%3}, {%4,%5,%6,%7}, {%8,%9}, {%0,%1,%2,%3};"
        : "+f"(c[0]), "+f"(c[1]), "+f"(c[2]), "+f"(c[3])
        : "r"(a[0]), "r"(a[1]), "r"(a[2]), "r"(a[3]), "r"(b0), "r"(b1));
}

__device__ __forceinline__ void ldsm_x4(uint32_t& r0, uint32_t& r1,
                                        uint32_t& r2, uint32_t& r3, uint32_t addr) {
    asm volatile("ldmatrix.sync.aligned.m8n8.x4.shared.b16 {%0,%1,%2,%3}, [%4];"
                 : "=r"(r0), "=r"(r1), "=r"(r2), "=r"(r3) : "r"(addr));
}
__device__ __forceinline__ void ldsm_x4t(uint32_t& r0, uint32_t& r1,
                                         uint32_t& r2, uint32_t& r3, uint32_t addr) {
    asm volatile("ldmatrix.sync.aligned.m8n8.x4.trans.shared.b16 {%0,%1,%2,%3}, [%4];"
                 : "=r"(r0), "=r"(r1), "=r"(r2), "=r"(r3) : "r"(addr));
}

__device__ __forceinline__ void cp_async16(uint32_t smem_dst, const void* gsrc) {
    asm volatile("cp.async.cg.shared.global [%0], [%1], 16;"
                 :: "r"(smem_dst), "l"(gsrc));
}
__device__ __forceinline__ void cp_commit() {
    asm volatile("cp.async.commit_group;");
}
template<int N>
__device__ __forceinline__ void cp_wait() {
    asm volatile("cp.async.wait_group %0;" :: "n"(N));
}

// ---------------- weight prep (fp32 -> bf16) ----------------
__global__ __launch_bounds__(256) void cvt_kernel(const float* __restrict__ in,
                                                  __nv_bfloat16* __restrict__ out, int n)
{
    int i = blockIdx.x * 256 + threadIdx.x;
    if (i < n) out[i] = __float2bfloat16_rn(in[i]);
}

// pack Wq|Wk|Wv side by side into [K=512][N=1536], bf16
__global__ __launch_bounds__(256) void cvt_qkv_kernel(
    const float* __restrict__ wq, const float* __restrict__ wk,
    const float* __restrict__ wv, __nv_bfloat16* __restrict__ out)
{
    int i = blockIdx.x * 256 + threadIdx.x;
    if (i < H_ * H_) {
        int k = i >> 9, n = i & 511;
        out[k * 1536 + n]        = __float2bfloat16_rn(wq[i]);
        out[k * 1536 + 512 + n]  = __float2bfloat16_rn(wk[i]);
        out[k * 1536 + 1024 + n] = __float2bfloat16_rn(wv[i]);
    }
}

__global__ __launch_bounds__(256) void cat_bias_kernel(
    const float* __restrict__ a, const float* __restrict__ b,
    const float* __restrict__ c, float* __restrict__ o)
{
    int i = blockIdx.x * 256 + threadIdx.x;
    if (i < 512) { o[i] = a[i]; o[i + 512] = b[i]; o[i + 1024] = c[i]; }
}

// fuse graph mask into attention bias: beff = mask ? bias : -1e9
__global__ __launch_bounds__(256) void fuse_bias_kernel(
    const float* __restrict__ bias, const int* __restrict__ mask,
    float* __restrict__ beff)
{
    long i = (long)blockIdx.x * 256 + threadIdx.x;
    beff[i] = mask[i] ? bias[i] : -1e9f;
}

// ---------------- LayerNorm (bf16 out) ----------------
__global__ __launch_bounds__(256) void ln_kernel(
    const float* __restrict__ x, const float* __restrict__ gam,
    const float* __restrict__ bet, __nv_bfloat16* __restrict__ y)
{
    int row = blockIdx.x;
    int t   = threadIdx.x;
    const float* xr = x + (long)row * H_;
    float a = xr[t];
    float b = xr[t + 256];
    float s = a + b;
    float q = a * a + b * b;
    #pragma unroll
    for (int off = 16; off > 0; off >>= 1) {
        s += __shfl_xor_sync(0xffffffffu, s, off);
        q += __shfl_xor_sync(0xffffffffu, q, off);
    }
    __shared__ float ss[8], qq[8];
    int w = t >> 5, lane = t & 31;
    if (lane == 0) { ss[w] = s; qq[w] = q; }
    __syncthreads();
    float S = 0.f, Q = 0.f;
    #pragma unroll
    for (int i = 0; i < 8; i++) { S += ss[i]; Q += qq[i]; }
    float mean = S * (1.f / H_);
    float var  = Q * (1.f / H_) - mean * mean;
    float inv  = rsqrtf(var + 1e-5f);
    __nv_bfloat16* yr = y + (long)row * H_;
    yr[t]       = __float2bfloat16_rn((a - mean) * inv * gam[t]       + bet[t]);
    yr[t + 256] = __float2bfloat16_rn((b - mean) * inv * gam[t + 256] + bet[t + 256]);
}

// ---------------- bf16 GEMM, ldmatrix + m16n8k16, cp.async 4-stage ----------------
#define ASTAGE 5120    // 128*40 bf16 per stage
#define BSTAGE 4352    // 32*136 bf16 per stage
#define NSTG   4
template<int MODE>
__global__ __launch_bounds__(256, 2) void gemm_tc(
    const __nv_bfloat16* __restrict__ A, const __nv_bfloat16* __restrict__ Bm,
    const float* __restrict__ bias, const float* __restrict__ res,
    void* __restrict__ CoutV, float* __restrict__ out2, float* __restrict__ out3,
    int Nd, int Kd)
{
    extern __shared__ __align__(16) __nv_bfloat16 smp[];
    __nv_bfloat16* As = smp;
    __nv_bfloat16* Bs = smp + NSTG * ASTAGE;

    const int tid = threadIdx.x;
    const int w   = tid >> 5;
    const int l   = tid & 31;
    const int wm  = w >> 2;
    const int wn  = w & 3;
    const int g   = l >> 2;
    const int tig = l & 3;

    const int bx = blockIdx.x, by = blockIdx.y;
    const __nv_bfloat16* Ab = A  + (long)(by * 128) * Kd;
    const __nv_bfloat16* Bb = Bm + bx * 128;

    const uint32_t sA = (uint32_t)__cvta_generic_to_shared(As);
    const uint32_t sB = (uint32_t)__cvta_generic_to_shared(Bs);

    const uint32_t aOff = ((uint32_t)(wm * 64 + (l & 15)) * 40) * 2 + (l >> 4) * 16;
    const uint32_t bOff = ((uint32_t)((l & 15)) * 136 + wn * 32) * 2 + (l >> 4) * 16;

    const int aRow = tid >> 1;
    const int aK   = (tid & 1) * 16;
    const int bRow = tid >> 3;
    const int bCol = (tid & 7) * 16;

    float acc[4][4][4];
    #pragma unroll
    for (int i = 0; i < 4; i++)
        #pragma unroll
        for (int j = 0; j < 4; j++)
            #pragma unroll
            for (int r = 0; r < 4; r++) acc[i][j][r] = 0.f;

    const int nK = Kd >> 5;

    auto issue = [&](int kt, int st) {
        const int k0 = kt * 32;
        uint32_t ad = sA + (st * ASTAGE + aRow * 40 + aK) * 2;
        const __nv_bfloat16* asrc = Ab + (long)aRow * Kd + k0 + aK;
        cp_async16(ad,      asrc);
        cp_async16(ad + 16, asrc + 8);
        uint32_t bd = sB + (st * BSTAGE + bRow * 136 + bCol) * 2;
        const __nv_bfloat16* bsrc = Bb + (long)(k0 + bRow) * Nd + bCol;
        cp_async16(bd,      bsrc);
        cp_async16(bd + 16, bsrc + 8);
        cp_commit();
    };

    issue(0, 0);
    issue(1, 1);
    if (nK > 2) issue(2, 2);
    else cp_commit();

    int st = 0;
    for (int kt = 0; kt < nK; kt++) {
        cp_wait<2>();
        __syncthreads();

        const uint32_t aB = sA + st * ASTAGE * 2 + aOff;
        const uint32_t bB = sB + st * BSTAGE * 2 + bOff;

        #pragma unroll
        for (int kc = 0; kc < 2; kc++) {
            uint32_t af[4][4], bf[2][4];
            #pragma unroll
            for (int mt = 0; mt < 4; mt++)
                ldsm_x4(af[mt][0], af[mt][1], af[mt][2], af[mt][3],
                        aB + mt * 1280 + kc * 32);
            #pragma unroll
            for (int np = 0; np < 2; np++)
                ldsm_x4t(bf[np][0], bf[np][1], bf[np][2], bf[np][3],
                         bB + kc * 4352 + np * 32);
            #pragma unroll
            for (int mt = 0; mt < 4; mt++)
                #pragma unroll
                for (int n8 = 0; n8 < 4; n8++) {
                    uint32_t b0 = bf[n8 >> 1][(n8 & 1) * 2];
                    uint32_t b1 = bf[n8 >> 1][(n8 & 1) * 2 + 1];
                    mma_bf16(acc[mt][n8], af[mt], b0, b1);
                }
        }

        if (kt + 3 < nK) {
            int nst = st + 3; if (nst >= NSTG) nst -= NSTG;
            issue(kt + 3, nst);
        } else {
            cp_commit();
        }
        st = st + 1 == NSTG ? 0 : st + 1;
    }

    // ---- epilogue ----
    float* Cf = (float*)CoutV;
    __nv_bfloat16* Ch = (__nv_bfloat16*)CoutV;
    int nbase = bx * 128;
    if (MODE == 0) {
        int proj = bx >> 2;
        Cf = proj == 0 ? (float*)CoutV : (proj == 1 ? out2 : out3);
    }
    #pragma unroll
    for (int mt = 0; mt < 4; mt++) {
        #pragma unroll
        for (int half = 0; half < 2; half++) {
            int mr = by * 128 + wm * 64 + mt * 16 + g + half * 8;
            #pragma unroll
            for (int nt = 0; nt < 4; nt++) {
                int nc = nbase + wn * 32 + nt * 8 + 2 * tig;
                float v0 = acc[mt][nt][half * 2 + 0] + bias[nc];
                float v1 = acc[mt][nt][half * 2 + 1] + bias[nc + 1];
                if (MODE == 0) {
                    int b = mr >> 10, s = mr & 1023;
                    int h = (nc & 511) >> 6, d = nc & 63;
                    long idx = ((long)((b * NH_ + h) << 10) + s) * DH_ + d;
                    *(float2*)&Cf[idx] = make_float2(v0, v1);
                } else if (MODE == 1) {
                    long idx = (long)mr * Nd + nc;
                    float2 rv = *(const float2*)&res[idx];
                    *(float2*)&Cf[idx] = make_float2(rv.x + v0, rv.y + v1);
                } else {
                    long idx = (long)mr * Nd + nc;
                    float g0 = 0.5f * v0 * (1.f + erff(v0 * 0.70710678118f));
                    float g1 = 0.5f * v1 * (1.f + erff(v1 * 0.70710678118f));
                    *(__nv_bfloat162*)&Ch[idx] = __floats2bfloat162_rn(g0, g1);
                }
            }
        }
    }
}

// ---------------- Tensor-core flash attention (tf32, fused bias) ----------------
__global__ __launch_bounds__(128) void attn_tc(
    const float* __restrict__ q, const float* __restrict__ k,
    const float* __restrict__ v, const float* __restrict__ beff,
    __nv_bfloat16* __restrict__ att)
{
    extern __shared__ float sm[];
    float* Qs = sm;
    float* Ks = sm + 64 * 68;
    float* Vs = Ks + 64 * 65;

    const int h = blockIdx.x, qt = blockIdx.y, b = blockIdx.z;
    const int tid = threadIdx.x;
    const int w = tid >> 5, l = tid & 31;
    const int g = l >> 2, tig = l & 3;

    const long headoff = (long)((b * NH_ + h) * S_) * DH_;
    const float* qg = q + headoff + (long)qt * 64 * DH_;
    const float* kg = k + headoff;
    const float* vg = v + headoff;

    #pragma unroll
    for (int j = 0; j < 16; j++) {
        int lin = tid + j * 128;
        int r = lin >> 5, c2 = (lin & 31) * 2;
        float2 qv = *(const float2*)(qg + r * 64 + c2);
        Qs[r * 68 + c2]     = to_tf32(qv.x * 0.125f);
        Qs[r * 68 + c2 + 1] = to_tf32(qv.y * 0.125f);
    }
    __syncthreads();

    const int qrow = w * 16 + g;
    uint32_t qf[8][4];
    #pragma unroll
    for (int kk = 0; kk < 8; kk++) {
        qf[kk][0] = __float_as_uint(Qs[ qrow      * 68 + kk * 8 + tig    ]);
        qf[kk][1] = __float_as_uint(Qs[(qrow + 8) * 68 + kk * 8 + tig    ]);
        qf[kk][2] = __float_as_uint(Qs[ qrow      * 68 + kk * 8 + tig + 4]);
        qf[kk][3] = __float_as_uint(Qs[(qrow + 8) * 68 + kk * 8 + tig + 4]);
    }
    __syncthreads();

    float of[8][4];
    #pragma unroll
    for (int nt = 0; nt < 8; nt++)
        #pragma unroll
        for (int r = 0; r < 4; r++) of[nt][r] = 0.f;
    float m0 = -3.0e38f, m1 = -3.0e38f, l0 = 0.f, l1 = 0.f;

    const long srow0 = (long)b * S_ + qt * 64 + w * 16 + g;
    const float* brow0 = beff + srow0 * S_;
    const float* brow1 = brow0 + 8L * S_;

    float* Ps = Qs;

    for (int kt = 0; kt < S_ / 64; kt++) {
        #pragma unroll
        for (int j = 0; j < 16; j++) {
            int lin = tid + j * 128;
            int r = lin >> 5, c2 = (lin & 31) * 2;
            float2 kv = *(const float2*)(kg + (long)(kt * 64 + r) * 64 + c2);
            Ks[(c2    ) * 65 + r] = to_tf32(kv.x);
            Ks[(c2 + 1) * 65 + r] = to_tf32(kv.y);
            float2 vv = *(const float2*)(vg + (long)(kt * 64 + r) * 64 + c2);
            *(float2*)&Vs[r * 66 + c2] = make_float2(to_tf32(vv.x), to_tf32(vv.y));
        }
        __syncthreads();

        float sacc[8][4];
        #pragma unroll
        for (int nt = 0; nt < 8; nt++)
            #pragma unroll
            for (int r = 0; r < 4; r++) sacc[nt][r] = 0.f;
        #pragma unroll
        for (int kk = 0; kk < 8; kk++) {
            #pragma unroll
            for (int nt = 0; nt < 8; nt++) {
                uint32_t b0 = __float_as_uint(Ks[(kk * 8 + tig    ) * 65 + nt * 8 + g]);
                uint32_t b1 = __float_as_uint(Ks[(kk * 8 + tig + 4) * 65 + nt * 8 + g]);
                mma_tf32(sacc[nt], qf[kk], b0, b1);
            }
        }

        float tmax0 = -3.0e38f, tmax1 = -3.0e38f;
        #pragma unroll
        for (int nt = 0; nt < 8; nt++) {
            int kc = kt * 64 + nt * 8 + 2 * tig;
            float2 bv0 = *(const float2*)(brow0 + kc);
            float2 bv1 = *(const float2*)(brow1 + kc);
            sacc[nt][0] += bv0.x;
            sacc[nt][1] += bv0.y;
            sacc[nt][2] += bv1.x;
            sacc[nt][3] += bv1.y;
            tmax0 = fmaxf(tmax0, fmaxf(sacc[nt][0], sacc[nt][1]));
            tmax1 = fmaxf(tmax1, fmaxf(sacc[nt][2], sacc[nt][3]));
        }
        tmax0 = fmaxf(tmax0, __shfl_xor_sync(0xffffffffu, tmax0, 1));
        tmax0 = fmaxf(tmax0, __shfl_xor_sync(0xffffffffu, tmax0, 2));
        tmax1 = fmaxf(tmax1, __shfl_xor_sync(0xffffffffu, tmax1, 1));
        tmax1 = fmaxf(tmax1, __shfl_xor_sync(0xffffffffu, tmax1, 2));
        float mn0 = fmaxf(m0, tmax0), mn1 = fmaxf(m1, tmax1);
        float c0 = __expf(m0 - mn0), c1 = __expf(m1 - mn1);
        l0 *= c0; l1 *= c1;
        m0 = mn0; m1 = mn1;
        #pragma unroll
        for (int nt = 0; nt < 8; nt++) {
            of[nt][0] *= c0; of[nt][1] *= c0;
            of[nt][2] *= c1; of[nt][3] *= c1;
            float p0 = __expf(sacc[nt][0] - m0);
            float p1 = __expf(sacc[nt][1] - m0);
            float p2 = __expf(sacc[nt][2] - m1);
            float p3 = __expf(sacc[nt][3] - m1);
            l0 += p0 + p1; l1 += p2 + p3;
            *(float2*)&Ps[ qrow      * 68 + nt * 8 + 2 * tig] =
                make_float2(to_tf32(p0), to_tf32(p1));
            *(float2*)&Ps[(qrow + 8) * 68 + nt * 8 + 2 * tig] =
                make_float2(to_tf32(p2), to_tf32(p3));
        }
        __syncwarp();

        #pragma unroll
        for (int kk = 0; kk < 8; kk++) {
            uint32_t pf[4];
            pf[0] = __float_as_uint(Ps[ qrow      * 68 + kk * 8 + tig    ]);
            pf[1] = __float_as_uint(Ps[(qrow + 8) * 68 + kk * 8 + tig    ]);
            pf[2] = __float_as_uint(Ps[ qrow      * 68 + kk * 8 + tig + 4]);
            pf[3] = __float_as_uint(Ps[(qrow + 8) * 68 + kk * 8 + tig + 4]);
            #pragma unroll
            for (int nt = 0; nt < 8; nt++) {
                uint32_t b0 = __float_as_uint(Vs[(kk * 8 + tig    ) * 66 + nt * 8 + g]);
                uint32_t b1 = __float_as_uint(Vs[(kk * 8 + tig + 4) * 66 + nt * 8 + g]);
                mma_tf32(of[nt], pf, b0, b1);
            }
        }
        __syncthreads();
    }

    l0 += __shfl_xor_sync(0xffffffffu, l0, 1);
    l0 += __shfl_xor_sync(0xffffffffu, l0, 2);
    l1 += __shfl_xor_sync(0xffffffffu, l1, 1);
    l1 += __shfl_xor_sync(0xffffffffu, l1, 2);
    float inv0 = 1.f / l0, inv1 = 1.f / l1;

    const long orow0 = (long)b * S_ + qt * 64 + w * 16 + g;
    #pragma unroll
    for (int nt = 0; nt < 8; nt++) {
        int col = h * 64 + nt * 8 + 2 * tig;
        *(__nv_bfloat162*)&att[ orow0      * H_ + col] =
            __floats2bfloat162_rn(of[nt][0] * inv0, of[nt][1] * inv0);
        *(__nv_bfloat162*)&att[(orow0 + 8) * H_ + col] =
            __floats2bfloat162_rn(of[nt][2] * inv1, of[nt][3] * inv1);
    }
}

// ---------------- launch ----------------
extern "C" void kernel_launch(void* const* d_in, const int* in_sizes, int n_in,
                              void* d_out, int out_size)
{
    const float* x     = (const float*)d_in[0];
    const float* abias = (const float*)d_in[1];
    const int*   gmask = (const int*)  d_in[2];
    const float* ln1g  = (const float*)d_in[3];
    const float* ln1b  = (const float*)d_in[4];
    const float* Wq    = (const float*)d_in[5];
    const float* bq    = (const float*)d_in[6];
    const float* Wk    = (const float*)d_in[7];
    const float* bk    = (const float*)d_in[8];
    const float* Wv    = (const float*)d_in[9];
    const float* bv    = (const float*)d_in[10];
    const float* Wo    = (const float*)d_in[11];
    const float* bo    = (const float*)d_in[12];
    const float* ln2g  = (const float*)d_in[13];
    const float* ln2b  = (const float*)d_in[14];
    const float* W1    = (const float*)d_in[15];
    const float* b1    = (const float*)d_in[16];
    const float* W2    = (const float*)d_in[17];
    const float* b2    = (const float*)d_in[18];
    float* out = (float*)d_out;

    __nv_bfloat16 *yb, *ab, *h1b, *wqkv, *wo, *w1, *w2;
    float *qb, *kb, *vb, *x1b, *bqkv, *beff;
    cudaGetSymbolAddress((void**)&yb,   g_y);
    cudaGetSymbolAddress((void**)&qb,   g_q);
    cudaGetSymbolAddress((void**)&kb,   g_k);
    cudaGetSymbolAddress((void**)&vb,   g_v);
    cudaGetSymbolAddress((void**)&ab,   g_att);
    cudaGetSymbolAddress((void**)&x1b,  g_x1);
    cudaGetSymbolAddress((void**)&h1b,  g_h1);
    cudaGetSymbolAddress((void**)&wqkv, g_wqkv);
    cudaGetSymbolAddress((void**)&bqkv, g_bqkv);
    cudaGetSymbolAddress((void**)&wo,   g_wo);
    cudaGetSymbolAddress((void**)&w1,   g_w1);
    cudaGetSymbolAddress((void**)&w2,   g_w2);
    cudaGetSymbolAddress((void**)&beff, g_beff);

    const int GEMM_SMEM = NSTG * (ASTAGE + BSTAGE) * 2;         // 75776 B
    const int ATTN_SMEM = (64 * 68 + 64 * 65 + 64 * 66) * 4;    // 50944 B
    static int attr_set = 0;
    if (!attr_set) {
        cudaFuncSetAttribute(gemm_tc<0>, cudaFuncAttributeMaxDynamicSharedMemorySize, GEMM_SMEM);
        cudaFuncSetAttribute(gemm_tc<1>, cudaFuncAttributeMaxDynamicSharedMemorySize, GEMM_SMEM);
        cudaFuncSetAttribute(gemm_tc<2>, cudaFuncAttributeMaxDynamicSharedMemorySize, GEMM_SMEM);
        cudaFuncSetAttribute(attn_tc,    cudaFuncAttributeMaxDynamicSharedMemorySize, ATTN_SMEM);
        attr_set = 1;
    }

    // launch order: #6 is the QKV GEMM so ncu (-s 5 -c 1) captures it
    ln_kernel<<<M_, 256>>>(x, ln1g, ln1b, yb);                               // 1
    cvt_qkv_kernel<<<(H_*H_ + 255)/256, 256>>>(Wq, Wk, Wv, wqkv);            // 2
    cat_bias_kernel<<<2, 256>>>(bq, bk, bv, bqkv);                           // 3
    cvt_kernel<<<(H_*H_ + 255)/256, 256>>>(Wo, wo, H_*H_);                   // 4
    fuse_bias_kernel<<<(B_*S_*S_)/256, 256>>>(abias, gmask, beff);           // 5
    gemm_tc<0><<<dim3(12, 64), 256, GEMM_SMEM>>>(yb, wqkv, bqkv, nullptr,    // 6
                                                 (void*)qb, kb, vb, 1536, H_);
    attn_tc<<<dim3(NH_, S_ / 64, B_), 128, ATTN_SMEM>>>(qb, kb, vb, beff, ab); // 7
    gemm_tc<1><<<dim3(4, 64), 256, GEMM_SMEM>>>(ab, wo, bo, x,               // 8
                                                (void*)x1b, nullptr, nullptr, H_, H_);
    ln_kernel<<<M_, 256>>>(x1b, ln2g, ln2b, yb);                             // 9
    cvt_kernel<<<(H_*FFN_ + 255)/256, 256>>>(W1, w1, H_*FFN_);               // 10
    gemm_tc<2><<<dim3(16, 64), 256, GEMM_SMEM>>>(yb, w1, b1, nullptr,        // 11
                                                 (void*)h1b, nullptr, nullptr, FFN_, H_);
    cvt_kernel<<<(FFN_*H_ + 255)/256, 256>>>(W2, w2, FFN_*H_);               // 12
    gemm_tc<1><<<dim3(4, 64), 256, GEMM_SMEM>>>(h1b, w2, b2, x1b,            // 13
                                                (void*)out, nullptr, nullptr, H_, FFN_);
}